// round 14
// baseline (speedup 1.0000x reference)
#include <cuda_runtime.h>
#include <cuda_bf16.h>
#include <mma.h>

using namespace nvcuda;

typedef unsigned long long u64;
typedef unsigned int u32;

#define NB 4
#define NS 2048
#define NF 512
#define NH 8
#define ND 64
#define NFILT 512
#define NM (NB*NS)

// ---------------- scratch (device globals; no allocation allowed) ----------
__device__ __nv_bfloat16 g_qh[(size_t)NB*NH*NS*ND];  // q hi [B,H,S,D] (pre-scaled 1/8)
__device__ __nv_bfloat16 g_ql[(size_t)NB*NH*NS*ND];
__device__ __nv_bfloat16 g_kh[(size_t)NB*NH*NS*ND];  // k hi [B,H,S,D]
__device__ __nv_bfloat16 g_kl[(size_t)NB*NH*NS*ND];
__device__ __nv_bfloat16 g_vth[(size_t)NB*NH*NS*ND]; // v hi TRANSPOSED [B,H,D,S]
__device__ __nv_bfloat16 g_vtl[(size_t)NB*NH*NS*ND];
__device__ __nv_bfloat16 g_chi[(size_t)NM*NFILT];    // concat hi [B,S,H*D]
__device__ __nv_bfloat16 g_clo[(size_t)NM*NFILT];
__device__ __nv_bfloat16 g_xh[3][(size_t)NM*NF];     // x_q/x_k/x_v hi
__device__ __nv_bfloat16 g_xl[3][(size_t)NM*NF];
__device__ __nv_bfloat16 g_wh[4][(size_t)512*512];   // Wq/Wk/Wv/Wo hi
__device__ __nv_bfloat16 g_wl[4][(size_t)512*512];

__device__ __forceinline__ u32 pack_bf2(float a, float b) {
    __nv_bfloat16 ha = __float2bfloat16(a), hb = __float2bfloat16(b);
    return (u32)__bfloat16_as_ushort(ha) | ((u32)__bfloat16_as_ushort(hb) << 16);
}

// mma.m16n8k16 row.col f32 += bf16*bf16
__device__ __forceinline__ void mma16816(float* c, const u32* a, u32 b0, u32 b1) {
    asm volatile(
        "mma.sync.aligned.m16n8k16.row.col.f32.bf16.bf16.f32 "
        "{%0,%1,%2,%3}, {%4,%5,%6,%7}, {%8,%9}, {%0,%1,%2,%3};"
        : "+f"(c[0]), "+f"(c[1]), "+f"(c[2]), "+f"(c[3])
        : "r"(a[0]), "r"(a[1]), "r"(a[2]), "r"(a[3]), "r"(b0), "r"(b1));
}

// ldmatrix x4 (four 8x8 b16 matrices)
__device__ __forceinline__ void ldsm4(u32& r0, u32& r1, u32& r2, u32& r3, u32 addr) {
    asm volatile("ldmatrix.sync.aligned.m8n8.x4.shared.b16 {%0,%1,%2,%3}, [%4];"
                 : "=r"(r0), "=r"(r1), "=r"(r2), "=r"(r3) : "r"(addr));
}

// cp.async 16B
__device__ __forceinline__ void cp16(void* sm, const void* gm) {
    u32 sa = (u32)__cvta_generic_to_shared(sm);
    asm volatile("cp.async.cg.shared.global [%0], [%1], 16;" :: "r"(sa), "l"(gm));
}
#define CP_COMMIT() asm volatile("cp.async.commit_group;" ::: "memory")
#define CP_WAIT0()  asm volatile("cp.async.wait_group 0;" ::: "memory")

// ---------------------------------------------------------------------------
// split_all: one launch splits all 7 fp32 inputs into hi/lo bf16.
// segments 0..2: x (4096 blocks each), 3..6: W (256 blocks each). grid 13312.
// ---------------------------------------------------------------------------
struct SplitArgs {
    const float* src[7];
    __nv_bfloat16* hi[7];
    __nv_bfloat16* lo[7];
};

__global__ __launch_bounds__(256) void split_all(SplitArgs a)
{
    int b = blockIdx.x, seg, i;
    if (b < 12288) { seg = b >> 12; i = (b & 4095) * 256 + threadIdx.x; }
    else           { seg = 3 + ((b - 12288) >> 8); i = ((b - 12288) & 255) * 256 + threadIdx.x; }
    float4 x = ((const float4*)a.src[seg])[i];
    float xv[4] = {x.x, x.y, x.z, x.w};
    unsigned short hw[4], lw[4];
    #pragma unroll
    for (int j = 0; j < 4; j++) {
        __nv_bfloat16 h = __float2bfloat16(xv[j]);
        __nv_bfloat16 l = __float2bfloat16(xv[j] - __bfloat162float(h));
        hw[j] = __bfloat16_as_ushort(h);
        lw[j] = __bfloat16_as_ushort(l);
    }
    ((uint2*)a.hi[seg])[i] = make_uint2((u32)hw[0] | ((u32)hw[1] << 16),
                                        (u32)hw[2] | ((u32)hw[3] << 16));
    ((uint2*)a.lo[seg])[i] = make_uint2((u32)lw[0] | ((u32)lw[1] << 16),
                                        (u32)lw[2] | ((u32)lw[3] << 16));
}

// ---------------------------------------------------------------------------
// GEMM core: 128x64 CTA tile, K-chunk 64, 2-stage cp.async (1 barrier / 48 MMA)
// dyn smem stage (bf16 elems): Ah[128][72], Al, Bh[64][72], Bl
// ---------------------------------------------------------------------------
#define ALD3 72
#define BLD 72
#define CLD 72
#define CLDT 132
#define S_AH 0
#define S_AL 9216
#define S_BH 18432
#define S_BL 23040
#define S_STG 27648                    // stage stride (elems)
#define GEMM_BYTES (2*S_STG*2 + 256)   // 110848

// prefetch one K=64 stage (12 cp16 per thread, one commit)
__device__ __forceinline__ void gemm_prefetch(
    __nv_bfloat16* stg, int tid,
    const __nv_bfloat16* Agh, const __nv_bfloat16* Agl,
    const __nv_bfloat16* Wbh, const __nv_bfloat16* Wbl,
    int k0, int ldw)
{
    int r = tid >> 1, off = (tid & 1) * 32;
    #pragma unroll
    for (int q = 0; q < 4; q++) {
        cp16(stg + S_AH + r * ALD3 + off + q * 8, Agh + (size_t)r * NF + k0 + off + q * 8);
        cp16(stg + S_AL + r * ALD3 + off + q * 8, Agl + (size_t)r * NF + k0 + off + q * 8);
    }
    int rB = tid >> 2, u = (tid & 3) * 16;
    cp16(stg + S_BH + rB * BLD + u,     Wbh + (size_t)(k0 + rB) * ldw + u);
    cp16(stg + S_BH + rB * BLD + u + 8, Wbh + (size_t)(k0 + rB) * ldw + u + 8);
    cp16(stg + S_BL + rB * BLD + u,     Wbl + (size_t)(k0 + rB) * ldw + u);
    cp16(stg + S_BL + rB * BLD + u + 8, Wbl + (size_t)(k0 + rB) * ldw + u + 8);
    CP_COMMIT();
}

__device__ __forceinline__ void gemm_mainloop(
    __nv_bfloat16* smb, int tid, int wr, int wc,
    const __nv_bfloat16* Agh, const __nv_bfloat16* Agl,
    const __nv_bfloat16* Wbh, const __nv_bfloat16* Wbl, int ldw,
    wmma::fragment<wmma::accumulator, 16, 16, 16, float> (&acc)[2][2])
{
    gemm_prefetch(smb, tid, Agh, Agl, Wbh, Wbl, 0, ldw);
    for (int k0 = 0; k0 < NF; k0 += 64) {
        const int st = (k0 >> 6) & 1;
        CP_WAIT0();
        __syncthreads();
        if (k0 + 64 < NF)
            gemm_prefetch(smb + (st ^ 1) * S_STG, tid, Agh, Agl, Wbh, Wbl, k0 + 64, ldw);
        const __nv_bfloat16* cb = smb + st * S_STG;
        #pragma unroll
        for (int kk = 0; kk < 4; kk++) {
            wmma::fragment<wmma::matrix_a, 16, 16, 16, __nv_bfloat16, wmma::row_major> a_hi[2], a_lo[2];
            wmma::fragment<wmma::matrix_b, 16, 16, 16, __nv_bfloat16, wmma::row_major> b_hi[2], b_lo[2];
            #pragma unroll
            for (int i = 0; i < 2; i++) {
                wmma::load_matrix_sync(a_hi[i], cb + S_AH + (wr * 32 + i * 16) * ALD3 + kk * 16, ALD3);
                wmma::load_matrix_sync(a_lo[i], cb + S_AL + (wr * 32 + i * 16) * ALD3 + kk * 16, ALD3);
                wmma::load_matrix_sync(b_hi[i], cb + S_BH + (kk * 16) * BLD + wc * 32 + i * 16, BLD);
                wmma::load_matrix_sync(b_lo[i], cb + S_BL + (kk * 16) * BLD + wc * 32 + i * 16, BLD);
            }
            #pragma unroll
            for (int i = 0; i < 2; i++)
                #pragma unroll
                for (int j = 0; j < 2; j++) {
                    wmma::mma_sync(acc[i][j], a_hi[i], b_hi[j], acc[i][j]);
                    wmma::mma_sync(acc[i][j], a_hi[i], b_lo[j], acc[i][j]);
                    wmma::mma_sync(acc[i][j], a_lo[i], b_hi[j], acc[i][j]);
                }
        }
    }
    __syncthreads();
}

// ---------------------------------------------------------------------------
// proj_gemm: merged q/k/v projections. grid (NM/128, 8, 3), block 256.
// ---------------------------------------------------------------------------
struct ProjArgs {
    const __nv_bfloat16 *xh[3], *xl[3], *wh[3], *wl[3];
    const float* bias[3];
    __nv_bfloat16 *oh[3], *ol[3];
};

__global__ __launch_bounds__(256, 2) void proj_gemm(ProjArgs pa)
{
    extern __shared__ __nv_bfloat16 smb[];
    float* Csm = (float*)smb;
    float* sB  = (float*)((char*)smb + 2 * S_STG * 2);

    const int tid = threadIdx.x;
    const int w = tid >> 5;
    const int wr = w & 3, wc = w >> 2;
    const int m0 = blockIdx.x * 128;
    const int ny = blockIdx.y;
    const int z  = blockIdx.z;
    const int ng0 = ny * 64;

    if (tid < 64) sB[tid] = pa.bias[z][ng0 + tid];

    const __nv_bfloat16* Agh = pa.xh[z] + (size_t)m0 * NF;
    const __nv_bfloat16* Agl = pa.xl[z] + (size_t)m0 * NF;
    const __nv_bfloat16* Wbh = pa.wh[z] + (size_t)ny * 512 * 64;
    const __nv_bfloat16* Wbl = pa.wl[z] + (size_t)ny * 512 * 64;

    wmma::fragment<wmma::accumulator, 16, 16, 16, float> acc[2][2];
    #pragma unroll
    for (int i = 0; i < 2; i++)
        #pragma unroll
        for (int j = 0; j < 2; j++) wmma::fill_fragment(acc[i][j], 0.0f);

    gemm_mainloop(smb, tid, wr, wc, Agh, Agl, Wbh, Wbl, 64, acc);

    const int bb = m0 >> 11, ss0 = m0 & (NS - 1);
    if (z == 2) {
        #pragma unroll
        for (int i = 0; i < 2; i++)
            #pragma unroll
            for (int j = 0; j < 2; j++)
                wmma::store_matrix_sync(
                    Csm + (wr * 32 + i * 16) + (wc * 32 + j * 16) * CLDT,
                    acc[i][j], CLDT, wmma::mem_col_major);
        __syncthreads();
        const int d = tid >> 2, sseg = (tid & 3) * 32;
        float bi = sB[d];
        const float* cs = Csm + d * CLDT + sseg;
        __nv_bfloat16* oh = pa.oh[2] + ((size_t)(bb * NH + ny) * ND + d) * NS + ss0 + sseg;
        __nv_bfloat16* ol = pa.ol[2] + ((size_t)(bb * NH + ny) * ND + d) * NS + ss0 + sseg;
        #pragma unroll
        for (int g = 0; g < 4; g++) {
            u32 hw[4], lw[4];
            #pragma unroll
            for (int q2 = 0; q2 < 4; q2++) {
                float a = cs[g * 8 + q2 * 2] + bi;
                float b = cs[g * 8 + q2 * 2 + 1] + bi;
                __nv_bfloat16 ha = __float2bfloat16(a), hb2 = __float2bfloat16(b);
                hw[q2] = (u32)__bfloat16_as_ushort(ha) | ((u32)__bfloat16_as_ushort(hb2) << 16);
                lw[q2] = pack_bf2(a - __bfloat162float(ha), b - __bfloat162float(hb2));
            }
            *(uint4*)(oh + g * 8) = make_uint4(hw[0], hw[1], hw[2], hw[3]);
            *(uint4*)(ol + g * 8) = make_uint4(lw[0], lw[1], lw[2], lw[3]);
        }
    } else {
        #pragma unroll
        for (int i = 0; i < 2; i++)
            #pragma unroll
            for (int j = 0; j < 2; j++)
                wmma::store_matrix_sync(
                    Csm + (wr * 32 + i * 16) * CLD + (wc * 32 + j * 16),
                    acc[i][j], CLD, wmma::mem_row_major);
        __syncthreads();
        const float sc = (z == 0) ? 0.125f : 1.0f;
        __nv_bfloat16* oh = pa.oh[z] + ((size_t)(bb * NH + ny) * NS + ss0) * ND;
        __nv_bfloat16* ol = pa.ol[z] + ((size_t)(bb * NH + ny) * NS + ss0) * ND;
        #pragma unroll
        for (int r = 0; r < 8; r++) {
            int u = r * 256 + tid;
            int row = u >> 4, c4 = (u & 15) << 2;
            const float* cs = Csm + row * CLD + c4;
            const float* bi = sB + c4;
            float vv[4];
            #pragma unroll
            for (int i = 0; i < 4; i++) vv[i] = (cs[i] + bi[i]) * sc;
            unsigned short hw[4], lw[4];
            #pragma unroll
            for (int i = 0; i < 4; i++) {
                __nv_bfloat16 h = __float2bfloat16(vv[i]);
                __nv_bfloat16 l = __float2bfloat16(vv[i] - __bfloat162float(h));
                hw[i] = __bfloat16_as_ushort(h);
                lw[i] = __bfloat16_as_ushort(l);
            }
            *(uint2*)(oh + (size_t)row * ND + c4) =
                make_uint2((u32)hw[0] | ((u32)hw[1] << 16), (u32)hw[2] | ((u32)hw[3] << 16));
            *(uint2*)(ol + (size_t)row * ND + c4) =
                make_uint2((u32)lw[0] | ((u32)lw[1] << 16), (u32)lw[2] | ((u32)lw[3] << 16));
        }
    }
}

// ---------------------------------------------------------------------------
// out_gemm: final C = concat @ Wo + bo (fp32 out). grid (NM/128, 8).
// ---------------------------------------------------------------------------
__global__ __launch_bounds__(256, 2) void out_gemm(
    const __nv_bfloat16* __restrict__ Ahi, const __nv_bfloat16* __restrict__ Alo,
    const __nv_bfloat16* __restrict__ Whi, const __nv_bfloat16* __restrict__ Wlo,
    const float* __restrict__ bias, float* __restrict__ out32)
{
    extern __shared__ __nv_bfloat16 smb[];
    float* Csm = (float*)smb;
    float* sB  = (float*)((char*)smb + 2 * S_STG * 2);

    const int tid = threadIdx.x;
    const int w = tid >> 5;
    const int wr = w & 3, wc = w >> 2;
    const int m0 = blockIdx.x * 128;
    const int ny = blockIdx.y;
    const int ng0 = ny * 64;

    if (tid < 64) sB[tid] = bias[ng0 + tid];

    const __nv_bfloat16* Agh = Ahi + (size_t)m0 * NFILT;
    const __nv_bfloat16* Agl = Alo + (size_t)m0 * NFILT;
    const __nv_bfloat16* Wbh = Whi + ng0;
    const __nv_bfloat16* Wbl = Wlo + ng0;

    wmma::fragment<wmma::accumulator, 16, 16, 16, float> acc[2][2];
    #pragma unroll
    for (int i = 0; i < 2; i++)
        #pragma unroll
        for (int j = 0; j < 2; j++) wmma::fill_fragment(acc[i][j], 0.0f);

    gemm_mainloop(smb, tid, wr, wc, Agh, Agl, Wbh, Wbl, 512, acc);

    #pragma unroll
    for (int i = 0; i < 2; i++)
        #pragma unroll
        for (int j = 0; j < 2; j++)
            wmma::store_matrix_sync(
                Csm + (wr * 32 + i * 16) * CLD + (wc * 32 + j * 16),
                acc[i][j], CLD, wmma::mem_row_major);
    __syncthreads();

    float* ob = out32 + (size_t)m0 * NFILT + ng0;
    #pragma unroll
    for (int r = 0; r < 8; r++) {
        int u = r * 256 + tid;
        int row = u >> 4, c4 = (u & 15) << 2;
        const float* cs = Csm + row * CLD + c4;
        const float* bi = sB + c4;
        *(float4*)(ob + (size_t)row * NFILT + c4) =
            make_float4(cs[0] + bi[0], cs[1] + bi[1], cs[2] + bi[2], cs[3] + bi[3]);
    }
}

// ---------------------------------------------------------------------------
// attn_fa2: FlashAttention-2, raw mma.m16n8k16, register P & O, cp.async
// double-buffered K/V stages, ldmatrix.x4 fragment loads. (unchanged R13)
// ---------------------------------------------------------------------------
#define TSTG 18432   // bf16 elems per stage
#define ATTN_BYTES (2 * TSTG * 2)

__global__ __launch_bounds__(256, 2) void attn_fa2(
    const __nv_bfloat16* __restrict__ qh, const __nv_bfloat16* __restrict__ ql,
    const __nv_bfloat16* __restrict__ kh, const __nv_bfloat16* __restrict__ kl,
    const __nv_bfloat16* __restrict__ vth, const __nv_bfloat16* __restrict__ vtl,
    __nv_bfloat16* __restrict__ chi, __nv_bfloat16* __restrict__ clo)
{
    extern __shared__ __nv_bfloat16 smb[];
    const u32 smb_u = (u32)__cvta_generic_to_shared(smb);

    const int tid = threadIdx.x;
    const int w = tid >> 5, lane = tid & 31;
    const int g = lane >> 2, t = lane & 3;
    const int bh = blockIdx.y, bb = bh >> 3, hh = bh & 7;
    const int s0 = blockIdx.x * 128;
    const int qr0 = s0 + w * 16;

    const u32 ro = (u32)((lane & 7) * 144 + (lane >> 3) * 16);

    const __nv_bfloat16* khb = kh + (size_t)bh * NS * ND;
    const __nv_bfloat16* klb = kl + (size_t)bh * NS * ND;
    const __nv_bfloat16* vhb = vth + (size_t)bh * ND * NS;  // [d][s]
    const __nv_bfloat16* vlb = vtl + (size_t)bh * ND * NS;

    const int r1 = tid >> 3, c1 = (tid & 7) * 8;
    const int r2 = r1 + 32;

    {
        __nv_bfloat16* sKh = smb; __nv_bfloat16* sKl = smb + 4608;
        __nv_bfloat16* sVh = smb + 9216; __nv_bfloat16* sVl = smb + 13824;
        cp16(sKh + r1 * 72 + c1, khb + (size_t)r1 * ND + c1);
        cp16(sKh + r2 * 72 + c1, khb + (size_t)r2 * ND + c1);
        cp16(sKl + r1 * 72 + c1, klb + (size_t)r1 * ND + c1);
        cp16(sKl + r2 * 72 + c1, klb + (size_t)r2 * ND + c1);
        cp16(sVh + r1 * 72 + c1, vhb + (size_t)r1 * NS + c1);
        cp16(sVh + r2 * 72 + c1, vhb + (size_t)r2 * NS + c1);
        cp16(sVl + r1 * 72 + c1, vlb + (size_t)r1 * NS + c1);
        cp16(sVl + r2 * 72 + c1, vlb + (size_t)r2 * NS + c1);
        CP_COMMIT();
    }

    u32 aqh[4][4], aql[4][4];
    {
        const __nv_bfloat16* q0h = qh + ((size_t)bh * NS + qr0 + g) * ND;
        const __nv_bfloat16* q8h = q0h + (size_t)8 * ND;
        const __nv_bfloat16* q0l = ql + ((size_t)bh * NS + qr0 + g) * ND;
        const __nv_bfloat16* q8l = q0l + (size_t)8 * ND;
        #pragma unroll
        for (int s = 0; s < 4; s++) {
            int c0 = 16 * s + 2 * t;
            aqh[s][0] = *(const u32*)(q0h + c0);
            aqh[s][1] = *(const u32*)(q8h + c0);
            aqh[s][2] = *(const u32*)(q0h + c0 + 8);
            aqh[s][3] = *(const u32*)(q8h + c0 + 8);
            aql[s][0] = *(const u32*)(q0l + c0);
            aql[s][1] = *(const u32*)(q8l + c0);
            aql[s][2] = *(const u32*)(q0l + c0 + 8);
            aql[s][3] = *(const u32*)(q8l + c0 + 8);
        }
    }

    float O[8][4];
    #pragma unroll
    for (int j = 0; j < 8; j++) { O[j][0] = O[j][1] = O[j][2] = O[j][3] = 0.0f; }
    float m0 = -1e30f, m1 = -1e30f, l0 = 0.0f, l1 = 0.0f;

    for (int kt = 0; kt < NS; kt += 64) {
        const int st = (kt >> 6) & 1;
        CP_WAIT0();
        __syncthreads();
        if (kt + 64 < NS) {
            __nv_bfloat16* nb = smb + (st ^ 1) * TSTG;
            __nv_bfloat16* sKh = nb; __nv_bfloat16* sKl = nb + 4608;
            __nv_bfloat16* sVh = nb + 9216; __nv_bfloat16* sVl = nb + 13824;
            int kn = kt + 64;
            cp16(sKh + r1 * 72 + c1, khb + (size_t)(kn + r1) * ND + c1);
            cp16(sKh + r2 * 72 + c1, khb + (size_t)(kn + r2) * ND + c1);
            cp16(sKl + r1 * 72 + c1, klb + (size_t)(kn + r1) * ND + c1);
            cp16(sKl + r2 * 72 + c1, klb + (size_t)(kn + r2) * ND + c1);
            cp16(sVh + r1 * 72 + c1, vhb + (size_t)r1 * NS + kn + c1);
            cp16(sVh + r2 * 72 + c1, vhb + (size_t)r2 * NS + kn + c1);
            cp16(sVl + r1 * 72 + c1, vlb + (size_t)r1 * NS + kn + c1);
            cp16(sVl + r2 * 72 + c1, vlb + (size_t)r2 * NS + kn + c1);
            CP_COMMIT();
        }
        const u32 cb_u = smb_u + (u32)(st * TSTG * 2);
        const u32 kh_u = cb_u,          kl_u = cb_u + 9216;
        const u32 vh_u = cb_u + 18432,  vl_u = cb_u + 27648;

        float c[8][4];
        #pragma unroll
        for (int j = 0; j < 8; j++) { c[j][0] = c[j][1] = c[j][2] = c[j][3] = 0.0f; }
        #pragma unroll
        for (int j = 0; j < 8; j++) {
            const u32 jb = (u32)(j * 1152) + ro;
            u32 bhr[8], blr[8];
            ldsm4(bhr[0], bhr[1], bhr[2], bhr[3], kh_u + jb);
            ldsm4(bhr[4], bhr[5], bhr[6], bhr[7], kh_u + jb + 64);
            ldsm4(blr[0], blr[1], blr[2], blr[3], kl_u + jb);
            ldsm4(blr[4], blr[5], blr[6], blr[7], kl_u + jb + 64);
            #pragma unroll
            for (int s = 0; s < 4; s++) {
                mma16816(c[j], aqh[s], bhr[2*s], bhr[2*s+1]);
                mma16816(c[j], aqh[s], blr[2*s], blr[2*s+1]);
                mma16816(c[j], aql[s], bhr[2*s], bhr[2*s+1]);
            }
        }

        float mx0 = c[0][0], mx1 = c[0][2];
        #pragma unroll
        for (int j = 0; j < 8; j++) {
            mx0 = fmaxf(mx0, fmaxf(c[j][0], c[j][1]));
            mx1 = fmaxf(mx1, fmaxf(c[j][2], c[j][3]));
        }
        mx0 = fmaxf(mx0, __shfl_xor_sync(0xffffffffu, mx0, 1));
        mx0 = fmaxf(mx0, __shfl_xor_sync(0xffffffffu, mx0, 2));
        mx1 = fmaxf(mx1, __shfl_xor_sync(0xffffffffu, mx1, 1));
        mx1 = fmaxf(mx1, __shfl_xor_sync(0xffffffffu, mx1, 2));
        float mn0 = fmaxf(m0, mx0), mn1 = fmaxf(m1, mx1);
        float al0 = __expf(m0 - mn0), al1 = __expf(m1 - mn1);
        m0 = mn0; m1 = mn1;
        float s0r = 0.0f, s1r = 0.0f;
        #pragma unroll
        for (int j = 0; j < 8; j++) {
            c[j][0] = __expf(c[j][0] - mn0); s0r += c[j][0];
            c[j][1] = __expf(c[j][1] - mn0); s0r += c[j][1];
            c[j][2] = __expf(c[j][2] - mn1); s1r += c[j][2];
            c[j][3] = __expf(c[j][3] - mn1); s1r += c[j][3];
        }
        s0r += __shfl_xor_sync(0xffffffffu, s0r, 1);
        s0r += __shfl_xor_sync(0xffffffffu, s0r, 2);
        s1r += __shfl_xor_sync(0xffffffffu, s1r, 1);
        s1r += __shfl_xor_sync(0xffffffffu, s1r, 2);
        l0 = l0 * al0 + s0r;
        l1 = l1 * al1 + s1r;
        #pragma unroll
        for (int j = 0; j < 8; j++) {
            O[j][0] *= al0; O[j][1] *= al0; O[j][2] *= al1; O[j][3] *= al1;
        }

        u32 ph[4][4], pl[4][4];
        #pragma unroll
        for (int s = 0; s < 4; s++) {
            #pragma unroll
            for (int hcell = 0; hcell < 2; hcell++) {
                int j = 2 * s + hcell;
                float p0 = c[j][0], p1 = c[j][1], p2 = c[j][2], p3 = c[j][3];
                __nv_bfloat16 h0 = __float2bfloat16(p0), h1 = __float2bfloat16(p1);
                __nv_bfloat16 h2 = __float2bfloat16(p2), h3 = __float2bfloat16(p3);
                ph[s][2 * hcell]     = (u32)__bfloat16_as_ushort(h0) | ((u32)__bfloat16_as_ushort(h1) << 16);
                ph[s][2 * hcell + 1] = (u32)__bfloat16_as_ushort(h2) | ((u32)__bfloat16_as_ushort(h3) << 16);
                pl[s][2 * hcell]     = pack_bf2(p0 - __bfloat162float(h0), p1 - __bfloat162float(h1));
                pl[s][2 * hcell + 1] = pack_bf2(p2 - __bfloat162float(h2), p3 - __bfloat162float(h3));
            }
        }

        #pragma unroll
        for (int j = 0; j < 8; j++) {
            const u32 jb = (u32)(j * 1152) + ro;
            u32 vhr[8], vlr[8];
            ldsm4(vhr[0], vhr[1], vhr[2], vhr[3], vh_u + jb);
            ldsm4(vhr[4], vhr[5], vhr[6], vhr[7], vh_u + jb + 64);
            ldsm4(vlr[0], vlr[1], vlr[2], vlr[3], vl_u + jb);
            ldsm4(vlr[4], vlr[5], vlr[6], vlr[7], vl_u + jb + 64);
            #pragma unroll
            for (int s = 0; s < 4; s++) {
                mma16816(O[j], ph[s], vhr[2*s], vhr[2*s+1]);
                mma16816(O[j], ph[s], vlr[2*s], vlr[2*s+1]);
                mma16816(O[j], pl[s], vhr[2*s], vhr[2*s+1]);
            }
        }
    }

    float inv0 = 1.0f / l0, inv1 = 1.0f / l1;
    size_t r0off = ((size_t)bb * NS + qr0 + g) * NFILT + hh * ND;
    size_t r8off = r0off + (size_t)8 * NFILT;
    #pragma unroll
    for (int j = 0; j < 8; j++) {
        int col = 8 * j + 2 * t;
        float v0 = O[j][0] * inv0, v1 = O[j][1] * inv0;
        float v2 = O[j][2] * inv1, v3 = O[j][3] * inv1;
        __nv_bfloat16 h0 = __float2bfloat16(v0), h1 = __float2bfloat16(v1);
        __nv_bfloat16 h2 = __float2bfloat16(v2), h3 = __float2bfloat16(v3);
        *(u32*)(chi + r0off + col) = (u32)__bfloat16_as_ushort(h0) | ((u32)__bfloat16_as_ushort(h1) << 16);
        *(u32*)(chi + r8off + col) = (u32)__bfloat16_as_ushort(h2) | ((u32)__bfloat16_as_ushort(h3) << 16);
        *(u32*)(clo + r0off + col) = pack_bf2(v0 - __bfloat162float(h0), v1 - __bfloat162float(h1));
        *(u32*)(clo + r8off + col) = pack_bf2(v2 - __bfloat162float(h2), v3 - __bfloat162float(h3));
    }
}

// ---------------------------------------------------------------------------
extern "C" void kernel_launch(void* const* d_in, const int* in_sizes, int n_in,
                              void* d_out, int out_size)
{
    (void)in_sizes; (void)n_in; (void)out_size;
    const float* x_q = (const float*)d_in[0];
    const float* x_k = (const float*)d_in[1];
    const float* x_v = (const float*)d_in[2];
    const float* Wq  = (const float*)d_in[3];
    const float* bq  = (const float*)d_in[4];
    const float* Wk  = (const float*)d_in[5];
    const float* bk  = (const float*)d_in[6];
    const float* Wv  = (const float*)d_in[7];
    const float* bv  = (const float*)d_in[8];
    const float* Wo  = (const float*)d_in[9];
    const float* bo  = (const float*)d_in[10];
    float* out = (float*)d_out;

    __nv_bfloat16 *qh, *ql, *kh, *kl, *vth, *vtl, *chi, *clo, *xh, *xl, *wh, *wl;
    cudaGetSymbolAddress((void**)&qh, g_qh);
    cudaGetSymbolAddress((void**)&ql, g_ql);
    cudaGetSymbolAddress((void**)&kh, g_kh);
    cudaGetSymbolAddress((void**)&kl, g_kl);
    cudaGetSymbolAddress((void**)&vth, g_vth);
    cudaGetSymbolAddress((void**)&vtl, g_vtl);
    cudaGetSymbolAddress((void**)&chi, g_chi);
    cudaGetSymbolAddress((void**)&clo, g_clo);
    cudaGetSymbolAddress((void**)&xh, g_xh);
    cudaGetSymbolAddress((void**)&xl, g_xl);
    cudaGetSymbolAddress((void**)&wh, g_wh);
    cudaGetSymbolAddress((void**)&wl, g_wl);

    const size_t XSZ = (size_t)NM * NF;
    const size_t WSZ = (size_t)512 * 512;

    static int once = 0;
    if (!once) {
        cudaFuncSetAttribute(attn_fa2,
                             cudaFuncAttributeMaxDynamicSharedMemorySize, ATTN_BYTES);
        cudaFuncSetAttribute(proj_gemm,
                             cudaFuncAttributeMaxDynamicSharedMemorySize, GEMM_BYTES);
        cudaFuncSetAttribute(out_gemm,
                             cudaFuncAttributeMaxDynamicSharedMemorySize, GEMM_BYTES);
        once = 1;
    }

    SplitArgs sa;
    sa.src[0] = x_q; sa.src[1] = x_k; sa.src[2] = x_v;
    sa.src[3] = Wq;  sa.src[4] = Wk;  sa.src[5] = Wv; sa.src[6] = Wo;
    for (int i = 0; i < 3; i++) { sa.hi[i] = xh + i * XSZ; sa.lo[i] = xl + i * XSZ; }
    for (int i = 0; i < 4; i++) { sa.hi[3 + i] = wh + i * WSZ; sa.lo[3 + i] = wl + i * WSZ; }
    split_all<<<13312, 256>>>(sa);

    ProjArgs pa;
    for (int i = 0; i < 3; i++) {
        pa.xh[i] = xh + i * XSZ; pa.xl[i] = xl + i * XSZ;
        pa.wh[i] = wh + i * WSZ; pa.wl[i] = wl + i * WSZ;
    }
    pa.bias[0] = bq; pa.bias[1] = bk; pa.bias[2] = bv;
    pa.oh[0] = qh;  pa.ol[0] = ql;
    pa.oh[1] = kh;  pa.ol[1] = kl;
    pa.oh[2] = vth; pa.ol[2] = vtl;
    proj_gemm<<<dim3(NM / 128, 8, 3), 256, GEMM_BYTES>>>(pa);

    attn_fa2<<<dim3(NS / 128, NB * NH), 256, ATTN_BYTES>>>(qh, ql, kh, kl, vth, vtl, chi, clo);

    out_gemm<<<dim3(NM / 128, 8), 256, GEMM_BYTES>>>(chi, clo, wh + 3 * WSZ, wl + 3 * WSZ, bo, out);
}

// round 15
// speedup vs baseline: 1.0425x; 1.0425x over previous
#include <cuda_runtime.h>
#include <cuda_bf16.h>
#include <mma.h>

using namespace nvcuda;

typedef unsigned long long u64;
typedef unsigned int u32;

#define NB 4
#define NS 2048
#define NF 512
#define NH 8
#define ND 64
#define NFILT 512
#define NM (NB*NS)

// ---------------- scratch (device globals; no allocation allowed) ----------
__device__ __nv_bfloat16 g_qh[(size_t)NB*NH*NS*ND];  // q hi [B,H,S,D] (pre-scaled 1/8)
__device__ __nv_bfloat16 g_ql[(size_t)NB*NH*NS*ND];
__device__ __nv_bfloat16 g_kh[(size_t)NB*NH*NS*ND];  // k hi [B,H,S,D]
__device__ __nv_bfloat16 g_kl[(size_t)NB*NH*NS*ND];
__device__ __nv_bfloat16 g_vth[(size_t)NB*NH*NS*ND]; // v hi TRANSPOSED [B,H,D,S]
__device__ __nv_bfloat16 g_vtl[(size_t)NB*NH*NS*ND];
__device__ __nv_bfloat16 g_chi[(size_t)NM*NFILT];    // concat hi [B,S,H*D]
__device__ __nv_bfloat16 g_clo[(size_t)NM*NFILT];
__device__ __nv_bfloat16 g_xh[3][(size_t)NM*NF];     // x_q/x_k/x_v hi
__device__ __nv_bfloat16 g_xl[3][(size_t)NM*NF];
__device__ __nv_bfloat16 g_wh[4][(size_t)512*512];   // Wq/Wk/Wv/Wo hi
__device__ __nv_bfloat16 g_wl[4][(size_t)512*512];

__device__ __forceinline__ u32 pack_bf2(float a, float b) {
    __nv_bfloat16 ha = __float2bfloat16(a), hb = __float2bfloat16(b);
    return (u32)__bfloat16_as_ushort(ha) | ((u32)__bfloat16_as_ushort(hb) << 16);
}

// mma.m16n8k16 row.col f32 += bf16*bf16
__device__ __forceinline__ void mma16816(float* c, const u32* a, u32 b0, u32 b1) {
    asm volatile(
        "mma.sync.aligned.m16n8k16.row.col.f32.bf16.bf16.f32 "
        "{%0,%1,%2,%3}, {%4,%5,%6,%7}, {%8,%9}, {%0,%1,%2,%3};"
        : "+f"(c[0]), "+f"(c[1]), "+f"(c[2]), "+f"(c[3])
        : "r"(a[0]), "r"(a[1]), "r"(a[2]), "r"(a[3]), "r"(b0), "r"(b1));
}

// ldmatrix x4 (four 8x8 b16 matrices)
__device__ __forceinline__ void ldsm4(u32& r0, u32& r1, u32& r2, u32& r3, u32 addr) {
    asm volatile("ldmatrix.sync.aligned.m8n8.x4.shared.b16 {%0,%1,%2,%3}, [%4];"
                 : "=r"(r0), "=r"(r1), "=r"(r2), "=r"(r3) : "r"(addr));
}

// cp.async 16B
__device__ __forceinline__ void cp16(void* sm, const void* gm) {
    u32 sa = (u32)__cvta_generic_to_shared(sm);
    asm volatile("cp.async.cg.shared.global [%0], [%1], 16;" :: "r"(sa), "l"(gm));
}
#define CP_COMMIT() asm volatile("cp.async.commit_group;" ::: "memory")
#define CP_WAIT0()  asm volatile("cp.async.wait_group 0;" ::: "memory")
#define CP_WAIT1()  asm volatile("cp.async.wait_group 1;" ::: "memory")

// ---------------------------------------------------------------------------
// split_all v2: 4 float4 units per thread (MLP=4), fully coalesced.
// x segs: 1024 blocks each (1Mi units / 1024 per block); W segs: 64 blocks.
// grid = 3*1024 + 4*64 = 3328.
// ---------------------------------------------------------------------------
struct SplitArgs {
    const float* src[7];
    __nv_bfloat16* hi[7];
    __nv_bfloat16* lo[7];
};

__global__ __launch_bounds__(256) void split_all(SplitArgs a)
{
    int b = blockIdx.x, seg, u0;
    if (b < 3072) { seg = b >> 10; u0 = (b & 1023) * 1024 + threadIdx.x; }
    else          { seg = 3 + ((b - 3072) >> 6); u0 = ((b - 3072) & 63) * 1024 + threadIdx.x; }
    const float4* src = (const float4*)a.src[seg];
    uint2* hip = (uint2*)a.hi[seg];
    uint2* lop = (uint2*)a.lo[seg];
    float4 x[4];
    #pragma unroll
    for (int q = 0; q < 4; q++) x[q] = src[u0 + q * 256];
    #pragma unroll
    for (int q = 0; q < 4; q++) {
        float xv[4] = {x[q].x, x[q].y, x[q].z, x[q].w};
        unsigned short hw[4], lw[4];
        #pragma unroll
        for (int j = 0; j < 4; j++) {
            __nv_bfloat16 h = __float2bfloat16(xv[j]);
            __nv_bfloat16 l = __float2bfloat16(xv[j] - __bfloat162float(h));
            hw[j] = __bfloat16_as_ushort(h);
            lw[j] = __bfloat16_as_ushort(l);
        }
        hip[u0 + q * 256] = make_uint2((u32)hw[0] | ((u32)hw[1] << 16),
                                       (u32)hw[2] | ((u32)hw[3] << 16));
        lop[u0 + q * 256] = make_uint2((u32)lw[0] | ((u32)lw[1] << 16),
                                       (u32)lw[2] | ((u32)lw[3] << 16));
    }
}

// ---------------------------------------------------------------------------
// GEMM core: 128x64 CTA tile, K-chunk 32, 3-stage cp.async, wait_group 1. (R13)
// ---------------------------------------------------------------------------
#define ALD2 40
#define BLD 72
#define CLD 72
#define CLDT 132
#define S_AH 0
#define S_AL 5120
#define S_BH 10240
#define S_BL 12544
#define S_STG 14848                  // stage stride (elems)
#define GEMM_BYTES (3*S_STG*2 + 256) // 89344

__device__ __forceinline__ void gemm_prefetch(
    __nv_bfloat16* stg, int tid,
    const __nv_bfloat16* Agh, const __nv_bfloat16* Agl,
    const __nv_bfloat16* Wbh, const __nv_bfloat16* Wbl,
    int k0, int ldw)
{
    int r = tid >> 1, off = (tid & 1) * 16;
    cp16(stg + S_AH + r * ALD2 + off,     Agh + (size_t)r * NF + k0 + off);
    cp16(stg + S_AH + r * ALD2 + off + 8, Agh + (size_t)r * NF + k0 + off + 8);
    cp16(stg + S_AL + r * ALD2 + off,     Agl + (size_t)r * NF + k0 + off);
    cp16(stg + S_AL + r * ALD2 + off + 8, Agl + (size_t)r * NF + k0 + off + 8);
    int rB = tid >> 3, u = (tid & 7) * 8;
    cp16(stg + S_BH + rB * BLD + u, Wbh + (size_t)(k0 + rB) * ldw + u);
    cp16(stg + S_BL + rB * BLD + u, Wbl + (size_t)(k0 + rB) * ldw + u);
    CP_COMMIT();
}

__device__ __forceinline__ void gemm_mainloop(
    __nv_bfloat16* smb, int tid, int wr, int wc,
    const __nv_bfloat16* Agh, const __nv_bfloat16* Agl,
    const __nv_bfloat16* Wbh, const __nv_bfloat16* Wbl, int ldw,
    wmma::fragment<wmma::accumulator, 16, 16, 16, float> (&acc)[2][2])
{
    gemm_prefetch(smb,         tid, Agh, Agl, Wbh, Wbl, 0,  ldw);
    gemm_prefetch(smb + S_STG, tid, Agh, Agl, Wbh, Wbl, 32, ldw);
    int st = 0;
    for (int k0 = 0; k0 < NF; k0 += 32) {
        CP_WAIT1();
        __syncthreads();
        if (k0 + 64 < NF) {
            int stn = st + 2; if (stn >= 3) stn -= 3;
            gemm_prefetch(smb + stn * S_STG, tid, Agh, Agl, Wbh, Wbl, k0 + 64, ldw);
        } else {
            CP_COMMIT();
        }
        const __nv_bfloat16* cb = smb + st * S_STG;
        #pragma unroll
        for (int kk = 0; kk < 2; kk++) {
            wmma::fragment<wmma::matrix_a, 16, 16, 16, __nv_bfloat16, wmma::row_major> a_hi[2], a_lo[2];
            wmma::fragment<wmma::matrix_b, 16, 16, 16, __nv_bfloat16, wmma::row_major> b_hi[2], b_lo[2];
            #pragma unroll
            for (int i = 0; i < 2; i++) {
                wmma::load_matrix_sync(a_hi[i], cb + S_AH + (wr * 32 + i * 16) * ALD2 + kk * 16, ALD2);
                wmma::load_matrix_sync(a_lo[i], cb + S_AL + (wr * 32 + i * 16) * ALD2 + kk * 16, ALD2);
                wmma::load_matrix_sync(b_hi[i], cb + S_BH + (kk * 16) * BLD + wc * 32 + i * 16, BLD);
                wmma::load_matrix_sync(b_lo[i], cb + S_BL + (kk * 16) * BLD + wc * 32 + i * 16, BLD);
            }
            #pragma unroll
            for (int i = 0; i < 2; i++)
                #pragma unroll
                for (int j = 0; j < 2; j++) {
                    wmma::mma_sync(acc[i][j], a_hi[i], b_hi[j], acc[i][j]);
                    wmma::mma_sync(acc[i][j], a_hi[i], b_lo[j], acc[i][j]);
                    wmma::mma_sync(acc[i][j], a_lo[i], b_hi[j], acc[i][j]);
                }
        }
        if (++st == 3) st = 0;
    }
    __syncthreads();
}

// ---------------------------------------------------------------------------
// proj_gemm: merged q/k/v projections. grid (NM/128, 8, 3), block 256.
// ---------------------------------------------------------------------------
struct ProjArgs {
    const __nv_bfloat16 *xh[3], *xl[3], *wh[3], *wl[3];
    const float* bias[3];
    __nv_bfloat16 *oh[3], *ol[3];
};

__global__ __launch_bounds__(256, 2) void proj_gemm(ProjArgs pa)
{
    extern __shared__ __nv_bfloat16 smb[];
    float* Csm = (float*)smb;
    float* sB  = (float*)((char*)smb + 3 * S_STG * 2);

    const int tid = threadIdx.x;
    const int w = tid >> 5;
    const int wr = w & 3, wc = w >> 2;
    const int m0 = blockIdx.x * 128;
    const int ny = blockIdx.y;
    const int z  = blockIdx.z;
    const int ng0 = ny * 64;

    if (tid < 64) sB[tid] = pa.bias[z][ng0 + tid];

    const __nv_bfloat16* Agh = pa.xh[z] + (size_t)m0 * NF;
    const __nv_bfloat16* Agl = pa.xl[z] + (size_t)m0 * NF;
    const __nv_bfloat16* Wbh = pa.wh[z] + (size_t)ny * 512 * 64;
    const __nv_bfloat16* Wbl = pa.wl[z] + (size_t)ny * 512 * 64;

    wmma::fragment<wmma::accumulator, 16, 16, 16, float> acc[2][2];
    #pragma unroll
    for (int i = 0; i < 2; i++)
        #pragma unroll
        for (int j = 0; j < 2; j++) wmma::fill_fragment(acc[i][j], 0.0f);

    gemm_mainloop(smb, tid, wr, wc, Agh, Agl, Wbh, Wbl, 64, acc);

    const int bb = m0 >> 11, ss0 = m0 & (NS - 1);
    if (z == 2) {
        #pragma unroll
        for (int i = 0; i < 2; i++)
            #pragma unroll
            for (int j = 0; j < 2; j++)
                wmma::store_matrix_sync(
                    Csm + (wr * 32 + i * 16) + (wc * 32 + j * 16) * CLDT,
                    acc[i][j], CLDT, wmma::mem_col_major);
        __syncthreads();
        const int d = tid >> 2, sseg = (tid & 3) * 32;
        float bi = sB[d];
        const float* cs = Csm + d * CLDT + sseg;
        __nv_bfloat16* oh = pa.oh[2] + ((size_t)(bb * NH + ny) * ND + d) * NS + ss0 + sseg;
        __nv_bfloat16* ol = pa.ol[2] + ((size_t)(bb * NH + ny) * ND + d) * NS + ss0 + sseg;
        #pragma unroll
        for (int g = 0; g < 4; g++) {
            u32 hw[4], lw[4];
            #pragma unroll
            for (int q2 = 0; q2 < 4; q2++) {
                float a = cs[g * 8 + q2 * 2] + bi;
                float b = cs[g * 8 + q2 * 2 + 1] + bi;
                __nv_bfloat16 ha = __float2bfloat16(a), hb2 = __float2bfloat16(b);
                hw[q2] = (u32)__bfloat16_as_ushort(ha) | ((u32)__bfloat16_as_ushort(hb2) << 16);
                lw[q2] = pack_bf2(a - __bfloat162float(ha), b - __bfloat162float(hb2));
            }
            *(uint4*)(oh + g * 8) = make_uint4(hw[0], hw[1], hw[2], hw[3]);
            *(uint4*)(ol + g * 8) = make_uint4(lw[0], lw[1], lw[2], lw[3]);
        }
    } else {
        #pragma unroll
        for (int i = 0; i < 2; i++)
            #pragma unroll
            for (int j = 0; j < 2; j++)
                wmma::store_matrix_sync(
                    Csm + (wr * 32 + i * 16) * CLD + (wc * 32 + j * 16),
                    acc[i][j], CLD, wmma::mem_row_major);
        __syncthreads();
        const float sc = (z == 0) ? 0.125f : 1.0f;
        __nv_bfloat16* oh = pa.oh[z] + ((size_t)(bb * NH + ny) * NS + ss0) * ND;
        __nv_bfloat16* ol = pa.ol[z] + ((size_t)(bb * NH + ny) * NS + ss0) * ND;
        #pragma unroll
        for (int r = 0; r < 8; r++) {
            int u = r * 256 + tid;
            int row = u >> 4, c4 = (u & 15) << 2;
            const float* cs = Csm + row * CLD + c4;
            const float* bi = sB + c4;
            float vv[4];
            #pragma unroll
            for (int i = 0; i < 4; i++) vv[i] = (cs[i] + bi[i]) * sc;
            unsigned short hw[4], lw[4];
            #pragma unroll
            for (int i = 0; i < 4; i++) {
                __nv_bfloat16 h = __float2bfloat16(vv[i]);
                __nv_bfloat16 l = __float2bfloat16(vv[i] - __bfloat162float(h));
                hw[i] = __bfloat16_as_ushort(h);
                lw[i] = __bfloat16_as_ushort(l);
            }
            *(uint2*)(oh + (size_t)row * ND + c4) =
                make_uint2((u32)hw[0] | ((u32)hw[1] << 16), (u32)hw[2] | ((u32)hw[3] << 16));
            *(uint2*)(ol + (size_t)row * ND + c4) =
                make_uint2((u32)lw[0] | ((u32)lw[1] << 16), (u32)lw[2] | ((u32)lw[3] << 16));
        }
    }
}

// ---------------------------------------------------------------------------
// out_gemm: final C = concat @ Wo + bo (fp32 out). grid (NM/128, 8).
// ---------------------------------------------------------------------------
__global__ __launch_bounds__(256, 2) void out_gemm(
    const __nv_bfloat16* __restrict__ Ahi, const __nv_bfloat16* __restrict__ Alo,
    const __nv_bfloat16* __restrict__ Whi, const __nv_bfloat16* __restrict__ Wlo,
    const float* __restrict__ bias, float* __restrict__ out32)
{
    extern __shared__ __nv_bfloat16 smb[];
    float* Csm = (float*)smb;
    float* sB  = (float*)((char*)smb + 3 * S_STG * 2);

    const int tid = threadIdx.x;
    const int w = tid >> 5;
    const int wr = w & 3, wc = w >> 2;
    const int m0 = blockIdx.x * 128;
    const int ny = blockIdx.y;
    const int ng0 = ny * 64;

    if (tid < 64) sB[tid] = bias[ng0 + tid];

    const __nv_bfloat16* Agh = Ahi + (size_t)m0 * NFILT;
    const __nv_bfloat16* Agl = Alo + (size_t)m0 * NFILT;
    const __nv_bfloat16* Wbh = Whi + ng0;
    const __nv_bfloat16* Wbl = Wlo + ng0;

    wmma::fragment<wmma::accumulator, 16, 16, 16, float> acc[2][2];
    #pragma unroll
    for (int i = 0; i < 2; i++)
        #pragma unroll
        for (int j = 0; j < 2; j++) wmma::fill_fragment(acc[i][j], 0.0f);

    gemm_mainloop(smb, tid, wr, wc, Agh, Agl, Wbh, Wbl, 512, acc);

    #pragma unroll
    for (int i = 0; i < 2; i++)
        #pragma unroll
        for (int j = 0; j < 2; j++)
            wmma::store_matrix_sync(
                Csm + (wr * 32 + i * 16) * CLD + (wc * 32 + j * 16),
                acc[i][j], CLD, wmma::mem_row_major);
    __syncthreads();

    float* ob = out32 + (size_t)m0 * NFILT + ng0;
    #pragma unroll
    for (int r = 0; r < 8; r++) {
        int u = r * 256 + tid;
        int row = u >> 4, c4 = (u & 15) << 2;
        const float* cs = Csm + row * CLD + c4;
        const float* bi = sB + c4;
        *(float4*)(ob + (size_t)row * NFILT + c4) =
            make_float4(cs[0] + bi[0], cs[1] + bi[1], cs[2] + bi[2], cs[3] + bi[3]);
    }
}

// ---------------------------------------------------------------------------
// attn_fa2: FlashAttention-2, raw mma.m16n8k16, register P & O, cp.async
// double-buffered K/V stages, ldmatrix.x4 fragment loads. (R13)
// ---------------------------------------------------------------------------
#define TSTG 18432   // bf16 elems per stage
#define ATTN_BYTES (2 * TSTG * 2)

__global__ __launch_bounds__(256, 2) void attn_fa2(
    const __nv_bfloat16* __restrict__ qh, const __nv_bfloat16* __restrict__ ql,
    const __nv_bfloat16* __restrict__ kh, const __nv_bfloat16* __restrict__ kl,
    const __nv_bfloat16* __restrict__ vth, const __nv_bfloat16* __restrict__ vtl,
    __nv_bfloat16* __restrict__ chi, __nv_bfloat16* __restrict__ clo)
{
    extern __shared__ __nv_bfloat16 smb[];
    const u32 smb_u = (u32)__cvta_generic_to_shared(smb);

    const int tid = threadIdx.x;
    const int w = tid >> 5, lane = tid & 31;
    const int g = lane >> 2, t = lane & 3;
    const int bh = blockIdx.y, bb = bh >> 3, hh = bh & 7;
    const int s0 = blockIdx.x * 128;
    const int qr0 = s0 + w * 16;

    const u32 ro = (u32)((lane & 7) * 144 + (lane >> 3) * 16);

    const __nv_bfloat16* khb = kh + (size_t)bh * NS * ND;
    const __nv_bfloat16* klb = kl + (size_t)bh * NS * ND;
    const __nv_bfloat16* vhb = vth + (size_t)bh * ND * NS;  // [d][s]
    const __nv_bfloat16* vlb = vtl + (size_t)bh * ND * NS;

    const int r1 = tid >> 3, c1 = (tid & 7) * 8;
    const int r2 = r1 + 32;

    {
        __nv_bfloat16* sKh = smb; __nv_bfloat16* sKl = smb + 4608;
        __nv_bfloat16* sVh = smb + 9216; __nv_bfloat16* sVl = smb + 13824;
        cp16(sKh + r1 * 72 + c1, khb + (size_t)r1 * ND + c1);
        cp16(sKh + r2 * 72 + c1, khb + (size_t)r2 * ND + c1);
        cp16(sKl + r1 * 72 + c1, klb + (size_t)r1 * ND + c1);
        cp16(sKl + r2 * 72 + c1, klb + (size_t)r2 * ND + c1);
        cp16(sVh + r1 * 72 + c1, vhb + (size_t)r1 * NS + c1);
        cp16(sVh + r2 * 72 + c1, vhb + (size_t)r2 * NS + c1);
        cp16(sVl + r1 * 72 + c1, vlb + (size_t)r1 * NS + c1);
        cp16(sVl + r2 * 72 + c1, vlb + (size_t)r2 * NS + c1);
        CP_COMMIT();
    }

    u32 aqh[4][4], aql[4][4];
    {
        const __nv_bfloat16* q0h = qh + ((size_t)bh * NS + qr0 + g) * ND;
        const __nv_bfloat16* q8h = q0h + (size_t)8 * ND;
        const __nv_bfloat16* q0l = ql + ((size_t)bh * NS + qr0 + g) * ND;
        const __nv_bfloat16* q8l = q0l + (size_t)8 * ND;
        #pragma unroll
        for (int s = 0; s < 4; s++) {
            int c0 = 16 * s + 2 * t;
            aqh[s][0] = *(const u32*)(q0h + c0);
            aqh[s][1] = *(const u32*)(q8h + c0);
            aqh[s][2] = *(const u32*)(q0h + c0 + 8);
            aqh[s][3] = *(const u32*)(q8h + c0 + 8);
            aql[s][0] = *(const u32*)(q0l + c0);
            aql[s][1] = *(const u32*)(q8l + c0);
            aql[s][2] = *(const u32*)(q0l + c0 + 8);
            aql[s][3] = *(const u32*)(q8l + c0 + 8);
        }
    }

    float O[8][4];
    #pragma unroll
    for (int j = 0; j < 8; j++) { O[j][0] = O[j][1] = O[j][2] = O[j][3] = 0.0f; }
    float m0 = -1e30f, m1 = -1e30f, l0 = 0.0f, l1 = 0.0f;

    for (int kt = 0; kt < NS; kt += 64) {
        const int st = (kt >> 6) & 1;
        CP_WAIT0();
        __syncthreads();
        if (kt + 64 < NS) {
            __nv_bfloat16* nb = smb + (st ^ 1) * TSTG;
            __nv_bfloat16* sKh = nb; __nv_bfloat16* sKl = nb + 4608;
            __nv_bfloat16* sVh = nb + 9216; __nv_bfloat16* sVl = nb + 13824;
            int kn = kt + 64;
            cp16(sKh + r1 * 72 + c1, khb + (size_t)(kn + r1) * ND + c1);
            cp16(sKh + r2 * 72 + c1, khb + (size_t)(kn + r2) * ND + c1);
            cp16(sKl + r1 * 72 + c1, klb + (size_t)(kn + r1) * ND + c1);
            cp16(sKl + r2 * 72 + c1, klb + (size_t)(kn + r2) * ND + c1);
            cp16(sVh + r1 * 72 + c1, vhb + (size_t)r1 * NS + kn + c1);
            cp16(sVh + r2 * 72 + c1, vhb + (size_t)r2 * NS + kn + c1);
            cp16(sVl + r1 * 72 + c1, vlb + (size_t)r1 * NS + kn + c1);
            cp16(sVl + r2 * 72 + c1, vlb + (size_t)r2 * NS + kn + c1);
            CP_COMMIT();
        }
        const u32 cb_u = smb_u + (u32)(st * TSTG * 2);
        const u32 kh_u = cb_u,          kl_u = cb_u + 9216;
        const u32 vh_u = cb_u + 18432,  vl_u = cb_u + 27648;

        float c[8][4];
        #pragma unroll
        for (int j = 0; j < 8; j++) { c[j][0] = c[j][1] = c[j][2] = c[j][3] = 0.0f; }
        #pragma unroll
        for (int j = 0; j < 8; j++) {
            const u32 jb = (u32)(j * 1152) + ro;
            u32 bhr[8], blr[8];
            ldsm4(bhr[0], bhr[1], bhr[2], bhr[3], kh_u + jb);
            ldsm4(bhr[4], bhr[5], bhr[6], bhr[7], kh_u + jb + 64);
            ldsm4(blr[0], blr[1], blr[2], blr[3], kl_u + jb);
            ldsm4(blr[4], blr[5], blr[6], blr[7], kl_u + jb + 64);
            #pragma unroll
            for (int s = 0; s < 4; s++) {
                mma16816(c[j], aqh[s], bhr[2*s], bhr[2*s+1]);
                mma16816(c[j], aqh[s], blr[2*s], blr[2*s+1]);
                mma16816(c[j], aql[s], bhr[2*s], bhr[2*s+1]);
            }
        }

        float mx0 = c[0][0], mx1 = c[0][2];
        #pragma unroll
        for (int j = 0; j < 8; j++) {
            mx0 = fmaxf(mx0, fmaxf(c[j][0], c[j][1]));
            mx1 = fmaxf(mx1, fmaxf(c[j][2], c[j][3]));
        }
        mx0 = fmaxf(mx0, __shfl_xor_sync(0xffffffffu, mx0, 1));
        mx0 = fmaxf(mx0, __shfl_xor_sync(0xffffffffu, mx0, 2));
        mx1 = fmaxf(mx1, __shfl_xor_sync(0xffffffffu, mx1, 1));
        mx1 = fmaxf(mx1, __shfl_xor_sync(0xffffffffu, mx1, 2));
        float mn0 = fmaxf(m0, mx0), mn1 = fmaxf(m1, mx1);
        float al0 = __expf(m0 - mn0), al1 = __expf(m1 - mn1);
        m0 = mn0; m1 = mn1;
        float s0r = 0.0f, s1r = 0.0f;
        #pragma unroll
        for (int j = 0; j < 8; j++) {
            c[j][0] = __expf(c[j][0] - mn0); s0r += c[j][0];
            c[j][1] = __expf(c[j][1] - mn0); s0r += c[j][1];
            c[j][2] = __expf(c[j][2] - mn1); s1r += c[j][2];
            c[j][3] = __expf(c[j][3] - mn1); s1r += c[j][3];
        }
        s0r += __shfl_xor_sync(0xffffffffu, s0r, 1);
        s0r += __shfl_xor_sync(0xffffffffu, s0r, 2);
        s1r += __shfl_xor_sync(0xffffffffu, s1r, 1);
        s1r += __shfl_xor_sync(0xffffffffu, s1r, 2);
        l0 = l0 * al0 + s0r;
        l1 = l1 * al1 + s1r;
        #pragma unroll
        for (int j = 0; j < 8; j++) {
            O[j][0] *= al0; O[j][1] *= al0; O[j][2] *= al1; O[j][3] *= al1;
        }

        u32 ph[4][4], pl[4][4];
        #pragma unroll
        for (int s = 0; s < 4; s++) {
            #pragma unroll
            for (int hcell = 0; hcell < 2; hcell++) {
                int j = 2 * s + hcell;
                float p0 = c[j][0], p1 = c[j][1], p2 = c[j][2], p3 = c[j][3];
                __nv_bfloat16 h0 = __float2bfloat16(p0), h1 = __float2bfloat16(p1);
                __nv_bfloat16 h2 = __float2bfloat16(p2), h3 = __float2bfloat16(p3);
                ph[s][2 * hcell]     = (u32)__bfloat16_as_ushort(h0) | ((u32)__bfloat16_as_ushort(h1) << 16);
                ph[s][2 * hcell + 1] = (u32)__bfloat16_as_ushort(h2) | ((u32)__bfloat16_as_ushort(h3) << 16);
                pl[s][2 * hcell]     = pack_bf2(p0 - __bfloat162float(h0), p1 - __bfloat162float(h1));
                pl[s][2 * hcell + 1] = pack_bf2(p2 - __bfloat162float(h2), p3 - __bfloat162float(h3));
            }
        }

        #pragma unroll
        for (int j = 0; j < 8; j++) {
            const u32 jb = (u32)(j * 1152) + ro;
            u32 vhr[8], vlr[8];
            ldsm4(vhr[0], vhr[1], vhr[2], vhr[3], vh_u + jb);
            ldsm4(vhr[4], vhr[5], vhr[6], vhr[7], vh_u + jb + 64);
            ldsm4(vlr[0], vlr[1], vlr[2], vlr[3], vl_u + jb);
            ldsm4(vlr[4], vlr[5], vlr[6], vlr[7], vl_u + jb + 64);
            #pragma unroll
            for (int s = 0; s < 4; s++) {
                mma16816(O[j], ph[s], vhr[2*s], vhr[2*s+1]);
                mma16816(O[j], ph[s], vlr[2*s], vlr[2*s+1]);
                mma16816(O[j], pl[s], vhr[2*s], vhr[2*s+1]);
            }
        }
    }

    float inv0 = 1.0f / l0, inv1 = 1.0f / l1;
    size_t r0off = ((size_t)bb * NS + qr0 + g) * NFILT + hh * ND;
    size_t r8off = r0off + (size_t)8 * NFILT;
    #pragma unroll
    for (int j = 0; j < 8; j++) {
        int col = 8 * j + 2 * t;
        float v0 = O[j][0] * inv0, v1 = O[j][1] * inv0;
        float v2 = O[j][2] * inv1, v3 = O[j][3] * inv1;
        __nv_bfloat16 h0 = __float2bfloat16(v0), h1 = __float2bfloat16(v1);
        __nv_bfloat16 h2 = __float2bfloat16(v2), h3 = __float2bfloat16(v3);
        *(u32*)(chi + r0off + col) = (u32)__bfloat16_as_ushort(h0) | ((u32)__bfloat16_as_ushort(h1) << 16);
        *(u32*)(chi + r8off + col) = (u32)__bfloat16_as_ushort(h2) | ((u32)__bfloat16_as_ushort(h3) << 16);
        *(u32*)(clo + r0off + col) = pack_bf2(v0 - __bfloat162float(h0), v1 - __bfloat162float(h1));
        *(u32*)(clo + r8off + col) = pack_bf2(v2 - __bfloat162float(h2), v3 - __bfloat162float(h3));
    }
}

// ---------------------------------------------------------------------------
extern "C" void kernel_launch(void* const* d_in, const int* in_sizes, int n_in,
                              void* d_out, int out_size)
{
    (void)in_sizes; (void)n_in; (void)out_size;
    const float* x_q = (const float*)d_in[0];
    const float* x_k = (const float*)d_in[1];
    const float* x_v = (const float*)d_in[2];
    const float* Wq  = (const float*)d_in[3];
    const float* bq  = (const float*)d_in[4];
    const float* Wk  = (const float*)d_in[5];
    const float* bk  = (const float*)d_in[6];
    const float* Wv  = (const float*)d_in[7];
    const float* bv  = (const float*)d_in[8];
    const float* Wo  = (const float*)d_in[9];
    const float* bo  = (const float*)d_in[10];
    float* out = (float*)d_out;

    __nv_bfloat16 *qh, *ql, *kh, *kl, *vth, *vtl, *chi, *clo, *xh, *xl, *wh, *wl;
    cudaGetSymbolAddress((void**)&qh, g_qh);
    cudaGetSymbolAddress((void**)&ql, g_ql);
    cudaGetSymbolAddress((void**)&kh, g_kh);
    cudaGetSymbolAddress((void**)&kl, g_kl);
    cudaGetSymbolAddress((void**)&vth, g_vth);
    cudaGetSymbolAddress((void**)&vtl, g_vtl);
    cudaGetSymbolAddress((void**)&chi, g_chi);
    cudaGetSymbolAddress((void**)&clo, g_clo);
    cudaGetSymbolAddress((void**)&xh, g_xh);
    cudaGetSymbolAddress((void**)&xl, g_xl);
    cudaGetSymbolAddress((void**)&wh, g_wh);
    cudaGetSymbolAddress((void**)&wl, g_wl);

    const size_t XSZ = (size_t)NM * NF;
    const size_t WSZ = (size_t)512 * 512;

    static int once = 0;
    if (!once) {
        cudaFuncSetAttribute(attn_fa2,
                             cudaFuncAttributeMaxDynamicSharedMemorySize, ATTN_BYTES);
        cudaFuncSetAttribute(proj_gemm,
                             cudaFuncAttributeMaxDynamicSharedMemorySize, GEMM_BYTES);
        cudaFuncSetAttribute(out_gemm,
                             cudaFuncAttributeMaxDynamicSharedMemorySize, GEMM_BYTES);
        once = 1;
    }

    SplitArgs sa;
    sa.src[0] = x_q; sa.src[1] = x_k; sa.src[2] = x_v;
    sa.src[3] = Wq;  sa.src[4] = Wk;  sa.src[5] = Wv; sa.src[6] = Wo;
    for (int i = 0; i < 3; i++) { sa.hi[i] = xh + i * XSZ; sa.lo[i] = xl + i * XSZ; }
    for (int i = 0; i < 4; i++) { sa.hi[3 + i] = wh + i * WSZ; sa.lo[3 + i] = wl + i * WSZ; }
    split_all<<<3328, 256>>>(sa);

    ProjArgs pa;
    for (int i = 0; i < 3; i++) {
        pa.xh[i] = xh + i * XSZ; pa.xl[i] = xl + i * XSZ;
        pa.wh[i] = wh + i * WSZ; pa.wl[i] = wl + i * WSZ;
    }
    pa.bias[0] = bq; pa.bias[1] = bk; pa.bias[2] = bv;
    pa.oh[0] = qh;  pa.ol[0] = ql;
    pa.oh[1] = kh;  pa.ol[1] = kl;
    pa.oh[2] = vth; pa.ol[2] = vtl;
    proj_gemm<<<dim3(NM / 128, 8, 3), 256, GEMM_BYTES>>>(pa);

    attn_fa2<<<dim3(NS / 128, NB * NH), 256, ATTN_BYTES>>>(qh, ql, kh, kl, vth, vtl, chi, clo);

    out_gemm<<<dim3(NM / 128, 8), 256, GEMM_BYTES>>>(chi, clo, wh + 3 * WSZ, wl + 3 * WSZ, bo, out);
}

// round 16
// speedup vs baseline: 1.0870x; 1.0427x over previous
#include <cuda_runtime.h>
#include <cuda_bf16.h>
#include <mma.h>

using namespace nvcuda;

typedef unsigned long long u64;
typedef unsigned int u32;

#define NB 4
#define NS 2048
#define NF 512
#define NH 8
#define ND 64
#define NFILT 512
#define NM (NB*NS)

// ---------------- scratch (device globals; no allocation allowed) ----------
__device__ __nv_bfloat16 g_qh[(size_t)NB*NH*NS*ND];  // q hi [B,H,S,D] (pre-scaled 1/8)
__device__ __nv_bfloat16 g_ql[(size_t)NB*NH*NS*ND];
__device__ __nv_bfloat16 g_kh[(size_t)NB*NH*NS*ND];  // k hi [B,H,S,D]
__device__ __nv_bfloat16 g_kl[(size_t)NB*NH*NS*ND];
__device__ __nv_bfloat16 g_vth[(size_t)NB*NH*NS*ND]; // v hi TRANSPOSED [B,H,D,S]
__device__ __nv_bfloat16 g_vtl[(size_t)NB*NH*NS*ND];
__device__ __nv_bfloat16 g_chi[(size_t)NM*NFILT];    // concat hi [B,S,H*D]
__device__ __nv_bfloat16 g_clo[(size_t)NM*NFILT];
__device__ __nv_bfloat16 g_xh[3][(size_t)NM*NF];     // x_q/x_k/x_v hi
__device__ __nv_bfloat16 g_xl[3][(size_t)NM*NF];
__device__ __nv_bfloat16 g_wh[4][(size_t)512*512];   // Wq/Wk/Wv/Wo hi
__device__ __nv_bfloat16 g_wl[4][(size_t)512*512];

__device__ __forceinline__ u32 pack_bf2(float a, float b) {
    __nv_bfloat16 ha = __float2bfloat16(a), hb = __float2bfloat16(b);
    return (u32)__bfloat16_as_ushort(ha) | ((u32)__bfloat16_as_ushort(hb) << 16);
}

// mma.m16n8k16 row.col f32 += bf16*bf16
__device__ __forceinline__ void mma16816(float* c, const u32* a, u32 b0, u32 b1) {
    asm volatile(
        "mma.sync.aligned.m16n8k16.row.col.f32.bf16.bf16.f32 "
        "{%0,%1,%2,%3}, {%4,%5,%6,%7}, {%8,%9}, {%0,%1,%2,%3};"
        : "+f"(c[0]), "+f"(c[1]), "+f"(c[2]), "+f"(c[3])
        : "r"(a[0]), "r"(a[1]), "r"(a[2]), "r"(a[3]), "r"(b0), "r"(b1));
}

// ldmatrix x4 (four 8x8 b16 matrices)
__device__ __forceinline__ void ldsm4(u32& r0, u32& r1, u32& r2, u32& r3, u32 addr) {
    asm volatile("ldmatrix.sync.aligned.m8n8.x4.shared.b16 {%0,%1,%2,%3}, [%4];"
                 : "=r"(r0), "=r"(r1), "=r"(r2), "=r"(r3) : "r"(addr));
}

// cp.async 16B
__device__ __forceinline__ void cp16(void* sm, const void* gm) {
    u32 sa = (u32)__cvta_generic_to_shared(sm);
    asm volatile("cp.async.cg.shared.global [%0], [%1], 16;" :: "r"(sa), "l"(gm));
}
#define CP_COMMIT() asm volatile("cp.async.commit_group;" ::: "memory")
#define CP_WAIT0()  asm volatile("cp.async.wait_group 0;" ::: "memory")

// ---------------------------------------------------------------------------
// split_all v2: 4 float4 units per thread (MLP=4), fully coalesced.
// grid = 3*1024 + 4*64 = 3328.
// ---------------------------------------------------------------------------
struct SplitArgs {
    const float* src[7];
    __nv_bfloat16* hi[7];
    __nv_bfloat16* lo[7];
};

__global__ __launch_bounds__(256) void split_all(SplitArgs a)
{
    int b = blockIdx.x, seg, u0;
    if (b < 3072) { seg = b >> 10; u0 = (b & 1023) * 1024 + threadIdx.x; }
    else          { seg = 3 + ((b - 3072) >> 6); u0 = ((b - 3072) & 63) * 1024 + threadIdx.x; }
    const float4* src = (const float4*)a.src[seg];
    uint2* hip = (uint2*)a.hi[seg];
    uint2* lop = (uint2*)a.lo[seg];
    float4 x[4];
    #pragma unroll
    for (int q = 0; q < 4; q++) x[q] = src[u0 + q * 256];
    #pragma unroll
    for (int q = 0; q < 4; q++) {
        float xv[4] = {x[q].x, x[q].y, x[q].z, x[q].w};
        unsigned short hw[4], lw[4];
        #pragma unroll
        for (int j = 0; j < 4; j++) {
            __nv_bfloat16 h = __float2bfloat16(xv[j]);
            __nv_bfloat16 l = __float2bfloat16(xv[j] - __bfloat162float(h));
            hw[j] = __bfloat16_as_ushort(h);
            lw[j] = __bfloat16_as_ushort(l);
        }
        hip[u0 + q * 256] = make_uint2((u32)hw[0] | ((u32)hw[1] << 16),
                                       (u32)hw[2] | ((u32)hw[3] << 16));
        lop[u0 + q * 256] = make_uint2((u32)lw[0] | ((u32)lw[1] << 16),
                                       (u32)lw[2] | ((u32)lw[3] << 16));
    }
}

// ---------------------------------------------------------------------------
// GEMM core v2: 128(M) x 128(N) CTA tile, K-chunk 32, 2-stage cp.async.
// Warps 4x2; warp tile 32x64 (acc[2][4]). 48 MMAs per warp per barrier.
// Stage (bf16 elems): Ah[128][40], Al, Bh[32][136], Bl.
// ---------------------------------------------------------------------------
#define ALD2 40
#define BLD2 136
#define CLDR 136
#define CLDC 132
#define S2_AH 0
#define S2_AL 5120
#define S2_BH 10240
#define S2_BL 14592
#define S2_STG 18944                   // stage stride (elems)
#define GEMM_BYTES (2*S2_STG*2 + 512)  // 76288

// prefetch one K=32 stage; B columns 0..63 from Wb0, 64..127 from Wb64
__device__ __forceinline__ void gemm_prefetch(
    __nv_bfloat16* stg, int tid,
    const __nv_bfloat16* Agh, const __nv_bfloat16* Agl,
    const __nv_bfloat16* Wb0h, const __nv_bfloat16* Wb64h,
    const __nv_bfloat16* Wb0l, const __nv_bfloat16* Wb64l,
    int k0, int ldw)
{
    int r = tid >> 1, off = (tid & 1) * 16;
    cp16(stg + S2_AH + r * ALD2 + off,     Agh + (size_t)r * NF + k0 + off);
    cp16(stg + S2_AH + r * ALD2 + off + 8, Agh + (size_t)r * NF + k0 + off + 8);
    cp16(stg + S2_AL + r * ALD2 + off,     Agl + (size_t)r * NF + k0 + off);
    cp16(stg + S2_AL + r * ALD2 + off + 8, Agl + (size_t)r * NF + k0 + off + 8);
    int rB = tid >> 3, u = (tid & 7) * 16;
    const __nv_bfloat16* bh = (u < 64 ? Wb0h : Wb64h) + (size_t)(k0 + rB) * ldw + (u & 63);
    const __nv_bfloat16* bl = (u < 64 ? Wb0l : Wb64l) + (size_t)(k0 + rB) * ldw + (u & 63);
    cp16(stg + S2_BH + rB * BLD2 + u,     bh);
    cp16(stg + S2_BH + rB * BLD2 + u + 8, bh + 8);
    cp16(stg + S2_BL + rB * BLD2 + u,     bl);
    cp16(stg + S2_BL + rB * BLD2 + u + 8, bl + 8);
    CP_COMMIT();
}

__device__ __forceinline__ void gemm_mainloop(
    __nv_bfloat16* smb, int tid, int wr, int wc,
    const __nv_bfloat16* Agh, const __nv_bfloat16* Agl,
    const __nv_bfloat16* Wb0h, const __nv_bfloat16* Wb64h,
    const __nv_bfloat16* Wb0l, const __nv_bfloat16* Wb64l, int ldw,
    wmma::fragment<wmma::accumulator, 16, 16, 16, float> (&acc)[2][4])
{
    gemm_prefetch(smb, tid, Agh, Agl, Wb0h, Wb64h, Wb0l, Wb64l, 0, ldw);
    for (int k0 = 0; k0 < NF; k0 += 32) {
        const int st = (k0 >> 5) & 1;
        CP_WAIT0();
        __syncthreads();
        if (k0 + 32 < NF)
            gemm_prefetch(smb + (st ^ 1) * S2_STG, tid,
                          Agh, Agl, Wb0h, Wb64h, Wb0l, Wb64l, k0 + 32, ldw);
        const __nv_bfloat16* cb = smb + st * S2_STG;
        #pragma unroll
        for (int kk = 0; kk < 2; kk++) {
            wmma::fragment<wmma::matrix_a, 16, 16, 16, __nv_bfloat16, wmma::row_major> a_hi[2], a_lo[2];
            #pragma unroll
            for (int i = 0; i < 2; i++) {
                wmma::load_matrix_sync(a_hi[i], cb + S2_AH + (wr * 32 + i * 16) * ALD2 + kk * 16, ALD2);
                wmma::load_matrix_sync(a_lo[i], cb + S2_AL + (wr * 32 + i * 16) * ALD2 + kk * 16, ALD2);
            }
            #pragma unroll
            for (int jn = 0; jn < 4; jn++) {
                wmma::fragment<wmma::matrix_b, 16, 16, 16, __nv_bfloat16, wmma::row_major> b_hi, b_lo;
                wmma::load_matrix_sync(b_hi, cb + S2_BH + (kk * 16) * BLD2 + wc * 64 + jn * 16, BLD2);
                wmma::load_matrix_sync(b_lo, cb + S2_BL + (kk * 16) * BLD2 + wc * 64 + jn * 16, BLD2);
                #pragma unroll
                for (int i = 0; i < 2; i++) {
                    wmma::mma_sync(acc[i][jn], a_hi[i], b_hi, acc[i][jn]);
                    wmma::mma_sync(acc[i][jn], a_hi[i], b_lo, acc[i][jn]);
                    wmma::mma_sync(acc[i][jn], a_lo[i], b_hi, acc[i][jn]);
                }
            }
        }
    }
    __syncthreads();
}

// ---------------------------------------------------------------------------
// proj_gemm: merged q/k/v projections, 2 heads per CTA.
// grid (NM/128, 4, 3), block 256. z=0 q (x0.125), z=1 k, z=2 v transposed.
// ---------------------------------------------------------------------------
struct ProjArgs {
    const __nv_bfloat16 *xh[3], *xl[3], *wh[3], *wl[3];
    const float* bias[3];
    __nv_bfloat16 *oh[3], *ol[3];
};

__global__ __launch_bounds__(256, 2) void proj_gemm(ProjArgs pa)
{
    extern __shared__ __nv_bfloat16 smb[];
    float* Csm = (float*)smb;
    float* sB  = (float*)((char*)smb + 2 * S2_STG * 2);

    const int tid = threadIdx.x;
    const int w = tid >> 5;
    const int wr = w & 3, wc = w >> 2;
    const int m0 = blockIdx.x * 128;
    const int ny = blockIdx.y;        // 0..3: heads 2ny, 2ny+1
    const int z  = blockIdx.z;

    if (tid < 128) sB[tid] = pa.bias[z][ny * 128 + tid];

    const __nv_bfloat16* Agh = pa.xh[z] + (size_t)m0 * NF;
    const __nv_bfloat16* Agl = pa.xl[z] + (size_t)m0 * NF;
    const __nv_bfloat16* Wb0h = pa.wh[z] + (size_t)(2 * ny) * 512 * 64;
    const __nv_bfloat16* Wb64h = Wb0h + (size_t)512 * 64;
    const __nv_bfloat16* Wb0l = pa.wl[z] + (size_t)(2 * ny) * 512 * 64;
    const __nv_bfloat16* Wb64l = Wb0l + (size_t)512 * 64;

    wmma::fragment<wmma::accumulator, 16, 16, 16, float> acc[2][4];
    #pragma unroll
    for (int i = 0; i < 2; i++)
        #pragma unroll
        for (int j = 0; j < 4; j++) wmma::fill_fragment(acc[i][j], 0.0f);

    gemm_mainloop(smb, tid, wr, wc, Agh, Agl, Wb0h, Wb64h, Wb0l, Wb64l, 64, acc);

    const int bb = m0 >> 11, ss0 = m0 & (NS - 1);
    if (z == 2) {
        // col-major store: Csm[m + n*CLDC]; epilogue writes [b,h,d,s]
        #pragma unroll
        for (int i = 0; i < 2; i++)
            #pragma unroll
            for (int j = 0; j < 4; j++)
                wmma::store_matrix_sync(
                    Csm + (wr * 32 + i * 16) + (wc * 64 + j * 16) * CLDC,
                    acc[i][j], CLDC, wmma::mem_col_major);
        __syncthreads();
        const int n = tid >> 1, sseg = (tid & 1) * 64;
        const int head = 2 * ny + (n >> 6), d = n & 63;
        float bi = sB[n];
        const float* cs = Csm + n * CLDC + sseg;
        __nv_bfloat16* oh = pa.oh[2] + ((size_t)(bb * NH + head) * ND + d) * NS + ss0 + sseg;
        __nv_bfloat16* ol = pa.ol[2] + ((size_t)(bb * NH + head) * ND + d) * NS + ss0 + sseg;
        #pragma unroll
        for (int g = 0; g < 8; g++) {
            u32 hw[4], lw[4];
            #pragma unroll
            for (int q2 = 0; q2 < 4; q2++) {
                float a = cs[g * 8 + q2 * 2] + bi;
                float b = cs[g * 8 + q2 * 2 + 1] + bi;
                __nv_bfloat16 ha = __float2bfloat16(a), hb2 = __float2bfloat16(b);
                hw[q2] = (u32)__bfloat16_as_ushort(ha) | ((u32)__bfloat16_as_ushort(hb2) << 16);
                lw[q2] = pack_bf2(a - __bfloat162float(ha), b - __bfloat162float(hb2));
            }
            *(uint4*)(oh + g * 8) = make_uint4(hw[0], hw[1], hw[2], hw[3]);
            *(uint4*)(ol + g * 8) = make_uint4(lw[0], lw[1], lw[2], lw[3]);
        }
    } else {
        #pragma unroll
        for (int i = 0; i < 2; i++)
            #pragma unroll
            for (int j = 0; j < 4; j++)
                wmma::store_matrix_sync(
                    Csm + (wr * 32 + i * 16) * CLDR + (wc * 64 + j * 16),
                    acc[i][j], CLDR, wmma::mem_row_major);
        __syncthreads();
        const float sc = (z == 0) ? 0.125f : 1.0f;
        #pragma unroll
        for (int r = 0; r < 16; r++) {
            int u = r * 256 + tid;               // 4096 4-col units
            int row = u >> 5, c4 = (u & 31) << 2;
            int head = 2 * ny + (c4 >> 6), hc = c4 & 63;
            const float* cs = Csm + row * CLDR + c4;
            const float* bi = sB + c4;
            float vv[4];
            #pragma unroll
            for (int i = 0; i < 4; i++) vv[i] = (cs[i] + bi[i]) * sc;
            unsigned short hw[4], lw[4];
            #pragma unroll
            for (int i = 0; i < 4; i++) {
                __nv_bfloat16 h = __float2bfloat16(vv[i]);
                __nv_bfloat16 l = __float2bfloat16(vv[i] - __bfloat162float(h));
                hw[i] = __bfloat16_as_ushort(h);
                lw[i] = __bfloat16_as_ushort(l);
            }
            size_t go = ((size_t)(bb * NH + head) * NS + ss0 + row) * ND + hc;
            *(uint2*)(pa.oh[z] + go) =
                make_uint2((u32)hw[0] | ((u32)hw[1] << 16), (u32)hw[2] | ((u32)hw[3] << 16));
            *(uint2*)(pa.ol[z] + go) =
                make_uint2((u32)lw[0] | ((u32)lw[1] << 16), (u32)lw[2] | ((u32)lw[3] << 16));
        }
    }
}

// ---------------------------------------------------------------------------
// out_gemm: final C = concat @ Wo + bo (fp32 out). grid (NM/128, 4).
// ---------------------------------------------------------------------------
__global__ __launch_bounds__(256, 2) void out_gemm(
    const __nv_bfloat16* __restrict__ Ahi, const __nv_bfloat16* __restrict__ Alo,
    const __nv_bfloat16* __restrict__ Whi, const __nv_bfloat16* __restrict__ Wlo,
    const float* __restrict__ bias, float* __restrict__ out32)
{
    extern __shared__ __nv_bfloat16 smb[];
    float* Csm = (float*)smb;
    float* sB  = (float*)((char*)smb + 2 * S2_STG * 2);

    const int tid = threadIdx.x;
    const int w = tid >> 5;
    const int wr = w & 3, wc = w >> 2;
    const int m0 = blockIdx.x * 128;
    const int ng0 = blockIdx.y * 128;

    if (tid < 128) sB[tid] = bias[ng0 + tid];

    const __nv_bfloat16* Agh = Ahi + (size_t)m0 * NFILT;
    const __nv_bfloat16* Agl = Alo + (size_t)m0 * NFILT;
    const __nv_bfloat16* Wb0h = Whi + ng0;
    const __nv_bfloat16* Wb64h = Wb0h + 64;
    const __nv_bfloat16* Wb0l = Wlo + ng0;
    const __nv_bfloat16* Wb64l = Wb0l + 64;

    wmma::fragment<wmma::accumulator, 16, 16, 16, float> acc[2][4];
    #pragma unroll
    for (int i = 0; i < 2; i++)
        #pragma unroll
        for (int j = 0; j < 4; j++) wmma::fill_fragment(acc[i][j], 0.0f);

    gemm_mainloop(smb, tid, wr, wc, Agh, Agl, Wb0h, Wb64h, Wb0l, Wb64l, 512, acc);

    #pragma unroll
    for (int i = 0; i < 2; i++)
        #pragma unroll
        for (int j = 0; j < 4; j++)
            wmma::store_matrix_sync(
                Csm + (wr * 32 + i * 16) * CLDR + (wc * 64 + j * 16),
                acc[i][j], CLDR, wmma::mem_row_major);
    __syncthreads();

    float* ob = out32 + (size_t)m0 * NFILT + ng0;
    #pragma unroll
    for (int r = 0; r < 16; r++) {
        int u = r * 256 + tid;
        int row = u >> 5, c4 = (u & 31) << 2;
        const float* cs = Csm + row * CLDR + c4;
        const float* bi = sB + c4;
        *(float4*)(ob + (size_t)row * NFILT + c4) =
            make_float4(cs[0] + bi[0], cs[1] + bi[1], cs[2] + bi[2], cs[3] + bi[3]);
    }
}

// ---------------------------------------------------------------------------
// attn_fa2: FlashAttention-2, raw mma.m16n8k16, register P & O, cp.async
// double-buffered K/V stages, ldmatrix.x4 fragment loads. (unchanged R15)
// ---------------------------------------------------------------------------
#define TSTG 18432   // bf16 elems per stage
#define ATTN_BYTES (2 * TSTG * 2)

__global__ __launch_bounds__(256, 2) void attn_fa2(
    const __nv_bfloat16* __restrict__ qh, const __nv_bfloat16* __restrict__ ql,
    const __nv_bfloat16* __restrict__ kh, const __nv_bfloat16* __restrict__ kl,
    const __nv_bfloat16* __restrict__ vth, const __nv_bfloat16* __restrict__ vtl,
    __nv_bfloat16* __restrict__ chi, __nv_bfloat16* __restrict__ clo)
{
    extern __shared__ __nv_bfloat16 smb[];
    const u32 smb_u = (u32)__cvta_generic_to_shared(smb);

    const int tid = threadIdx.x;
    const int w = tid >> 5, lane = tid & 31;
    const int g = lane >> 2, t = lane & 3;
    const int bh = blockIdx.y, bb = bh >> 3, hh = bh & 7;
    const int s0 = blockIdx.x * 128;
    const int qr0 = s0 + w * 16;

    const u32 ro = (u32)((lane & 7) * 144 + (lane >> 3) * 16);

    const __nv_bfloat16* khb = kh + (size_t)bh * NS * ND;
    const __nv_bfloat16* klb = kl + (size_t)bh * NS * ND;
    const __nv_bfloat16* vhb = vth + (size_t)bh * ND * NS;  // [d][s]
    const __nv_bfloat16* vlb = vtl + (size_t)bh * ND * NS;

    const int r1 = tid >> 3, c1 = (tid & 7) * 8;
    const int r2 = r1 + 32;

    {
        __nv_bfloat16* sKh = smb; __nv_bfloat16* sKl = smb + 4608;
        __nv_bfloat16* sVh = smb + 9216; __nv_bfloat16* sVl = smb + 13824;
        cp16(sKh + r1 * 72 + c1, khb + (size_t)r1 * ND + c1);
        cp16(sKh + r2 * 72 + c1, khb + (size_t)r2 * ND + c1);
        cp16(sKl + r1 * 72 + c1, klb + (size_t)r1 * ND + c1);
        cp16(sKl + r2 * 72 + c1, klb + (size_t)r2 * ND + c1);
        cp16(sVh + r1 * 72 + c1, vhb + (size_t)r1 * NS + c1);
        cp16(sVh + r2 * 72 + c1, vhb + (size_t)r2 * NS + c1);
        cp16(sVl + r1 * 72 + c1, vlb + (size_t)r1 * NS + c1);
        cp16(sVl + r2 * 72 + c1, vlb + (size_t)r2 * NS + c1);
        CP_COMMIT();
    }

    u32 aqh[4][4], aql[4][4];
    {
        const __nv_bfloat16* q0h = qh + ((size_t)bh * NS + qr0 + g) * ND;
        const __nv_bfloat16* q8h = q0h + (size_t)8 * ND;
        const __nv_bfloat16* q0l = ql + ((size_t)bh * NS + qr0 + g) * ND;
        const __nv_bfloat16* q8l = q0l + (size_t)8 * ND;
        #pragma unroll
        for (int s = 0; s < 4; s++) {
            int c0 = 16 * s + 2 * t;
            aqh[s][0] = *(const u32*)(q0h + c0);
            aqh[s][1] = *(const u32*)(q8h + c0);
            aqh[s][2] = *(const u32*)(q0h + c0 + 8);
            aqh[s][3] = *(const u32*)(q8h + c0 + 8);
            aql[s][0] = *(const u32*)(q0l + c0);
            aql[s][1] = *(const u32*)(q8l + c0);
            aql[s][2] = *(const u32*)(q0l + c0 + 8);
            aql[s][3] = *(const u32*)(q8l + c0 + 8);
        }
    }

    float O[8][4];
    #pragma unroll
    for (int j = 0; j < 8; j++) { O[j][0] = O[j][1] = O[j][2] = O[j][3] = 0.0f; }
    float m0 = -1e30f, m1 = -1e30f, l0 = 0.0f, l1 = 0.0f;

    for (int kt = 0; kt < NS; kt += 64) {
        const int st = (kt >> 6) & 1;
        CP_WAIT0();
        __syncthreads();
        if (kt + 64 < NS) {
            __nv_bfloat16* nb = smb + (st ^ 1) * TSTG;
            __nv_bfloat16* sKh = nb; __nv_bfloat16* sKl = nb + 4608;
            __nv_bfloat16* sVh = nb + 9216; __nv_bfloat16* sVl = nb + 13824;
            int kn = kt + 64;
            cp16(sKh + r1 * 72 + c1, khb + (size_t)(kn + r1) * ND + c1);
            cp16(sKh + r2 * 72 + c1, khb + (size_t)(kn + r2) * ND + c1);
            cp16(sKl + r1 * 72 + c1, klb + (size_t)(kn + r1) * ND + c1);
            cp16(sKl + r2 * 72 + c1, klb + (size_t)(kn + r2) * ND + c1);
            cp16(sVh + r1 * 72 + c1, vhb + (size_t)r1 * NS + kn + c1);
            cp16(sVh + r2 * 72 + c1, vhb + (size_t)r2 * NS + kn + c1);
            cp16(sVl + r1 * 72 + c1, vlb + (size_t)r1 * NS + kn + c1);
            cp16(sVl + r2 * 72 + c1, vlb + (size_t)r2 * NS + kn + c1);
            CP_COMMIT();
        }
        const u32 cb_u = smb_u + (u32)(st * TSTG * 2);
        const u32 kh_u = cb_u,          kl_u = cb_u + 9216;
        const u32 vh_u = cb_u + 18432,  vl_u = cb_u + 27648;

        float c[8][4];
        #pragma unroll
        for (int j = 0; j < 8; j++) { c[j][0] = c[j][1] = c[j][2] = c[j][3] = 0.0f; }
        #pragma unroll
        for (int j = 0; j < 8; j++) {
            const u32 jb = (u32)(j * 1152) + ro;
            u32 bhr[8], blr[8];
            ldsm4(bhr[0], bhr[1], bhr[2], bhr[3], kh_u + jb);
            ldsm4(bhr[4], bhr[5], bhr[6], bhr[7], kh_u + jb + 64);
            ldsm4(blr[0], blr[1], blr[2], blr[3], kl_u + jb);
            ldsm4(blr[4], blr[5], blr[6], blr[7], kl_u + jb + 64);
            #pragma unroll
            for (int s = 0; s < 4; s++) {
                mma16816(c[j], aqh[s], bhr[2*s], bhr[2*s+1]);
                mma16816(c[j], aqh[s], blr[2*s], blr[2*s+1]);
                mma16816(c[j], aql[s], bhr[2*s], bhr[2*s+1]);
            }
        }

        float mx0 = c[0][0], mx1 = c[0][2];
        #pragma unroll
        for (int j = 0; j < 8; j++) {
            mx0 = fmaxf(mx0, fmaxf(c[j][0], c[j][1]));
            mx1 = fmaxf(mx1, fmaxf(c[j][2], c[j][3]));
        }
        mx0 = fmaxf(mx0, __shfl_xor_sync(0xffffffffu, mx0, 1));
        mx0 = fmaxf(mx0, __shfl_xor_sync(0xffffffffu, mx0, 2));
        mx1 = fmaxf(mx1, __shfl_xor_sync(0xffffffffu, mx1, 1));
        mx1 = fmaxf(mx1, __shfl_xor_sync(0xffffffffu, mx1, 2));
        float mn0 = fmaxf(m0, mx0), mn1 = fmaxf(m1, mx1);
        float al0 = __expf(m0 - mn0), al1 = __expf(m1 - mn1);
        m0 = mn0; m1 = mn1;
        float s0r = 0.0f, s1r = 0.0f;
        #pragma unroll
        for (int j = 0; j < 8; j++) {
            c[j][0] = __expf(c[j][0] - mn0); s0r += c[j][0];
            c[j][1] = __expf(c[j][1] - mn0); s0r += c[j][1];
            c[j][2] = __expf(c[j][2] - mn1); s1r += c[j][2];
            c[j][3] = __expf(c[j][3] - mn1); s1r += c[j][3];
        }
        s0r += __shfl_xor_sync(0xffffffffu, s0r, 1);
        s0r += __shfl_xor_sync(0xffffffffu, s0r, 2);
        s1r += __shfl_xor_sync(0xffffffffu, s1r, 1);
        s1r += __shfl_xor_sync(0xffffffffu, s1r, 2);
        l0 = l0 * al0 + s0r;
        l1 = l1 * al1 + s1r;
        #pragma unroll
        for (int j = 0; j < 8; j++) {
            O[j][0] *= al0; O[j][1] *= al0; O[j][2] *= al1; O[j][3] *= al1;
        }

        u32 ph[4][4], pl[4][4];
        #pragma unroll
        for (int s = 0; s < 4; s++) {
            #pragma unroll
            for (int hcell = 0; hcell < 2; hcell++) {
                int j = 2 * s + hcell;
                float p0 = c[j][0], p1 = c[j][1], p2 = c[j][2], p3 = c[j][3];
                __nv_bfloat16 h0 = __float2bfloat16(p0), h1 = __float2bfloat16(p1);
                __nv_bfloat16 h2 = __float2bfloat16(p2), h3 = __float2bfloat16(p3);
                ph[s][2 * hcell]     = (u32)__bfloat16_as_ushort(h0) | ((u32)__bfloat16_as_ushort(h1) << 16);
                ph[s][2 * hcell + 1] = (u32)__bfloat16_as_ushort(h2) | ((u32)__bfloat16_as_ushort(h3) << 16);
                pl[s][2 * hcell]     = pack_bf2(p0 - __bfloat162float(h0), p1 - __bfloat162float(h1));
                pl[s][2 * hcell + 1] = pack_bf2(p2 - __bfloat162float(h2), p3 - __bfloat162float(h3));
            }
        }

        #pragma unroll
        for (int j = 0; j < 8; j++) {
            const u32 jb = (u32)(j * 1152) + ro;
            u32 vhr[8], vlr[8];
            ldsm4(vhr[0], vhr[1], vhr[2], vhr[3], vh_u + jb);
            ldsm4(vhr[4], vhr[5], vhr[6], vhr[7], vh_u + jb + 64);
            ldsm4(vlr[0], vlr[1], vlr[2], vlr[3], vl_u + jb);
            ldsm4(vlr[4], vlr[5], vlr[6], vlr[7], vl_u + jb + 64);
            #pragma unroll
            for (int s = 0; s < 4; s++) {
                mma16816(O[j], ph[s], vhr[2*s], vhr[2*s+1]);
                mma16816(O[j], ph[s], vlr[2*s], vlr[2*s+1]);
                mma16816(O[j], pl[s], vhr[2*s], vhr[2*s+1]);
            }
        }
    }

    float inv0 = 1.0f / l0, inv1 = 1.0f / l1;
    size_t r0off = ((size_t)bb * NS + qr0 + g) * NFILT + hh * ND;
    size_t r8off = r0off + (size_t)8 * NFILT;
    #pragma unroll
    for (int j = 0; j < 8; j++) {
        int col = 8 * j + 2 * t;
        float v0 = O[j][0] * inv0, v1 = O[j][1] * inv0;
        float v2 = O[j][2] * inv1, v3 = O[j][3] * inv1;
        __nv_bfloat16 h0 = __float2bfloat16(v0), h1 = __float2bfloat16(v1);
        __nv_bfloat16 h2 = __float2bfloat16(v2), h3 = __float2bfloat16(v3);
        *(u32*)(chi + r0off + col) = (u32)__bfloat16_as_ushort(h0) | ((u32)__bfloat16_as_ushort(h1) << 16);
        *(u32*)(chi + r8off + col) = (u32)__bfloat16_as_ushort(h2) | ((u32)__bfloat16_as_ushort(h3) << 16);
        *(u32*)(clo + r0off + col) = pack_bf2(v0 - __bfloat162float(h0), v1 - __bfloat162float(h1));
        *(u32*)(clo + r8off + col) = pack_bf2(v2 - __bfloat162float(h2), v3 - __bfloat162float(h3));
    }
}

// ---------------------------------------------------------------------------
extern "C" void kernel_launch(void* const* d_in, const int* in_sizes, int n_in,
                              void* d_out, int out_size)
{
    (void)in_sizes; (void)n_in; (void)out_size;
    const float* x_q = (const float*)d_in[0];
    const float* x_k = (const float*)d_in[1];
    const float* x_v = (const float*)d_in[2];
    const float* Wq  = (const float*)d_in[3];
    const float* bq  = (const float*)d_in[4];
    const float* Wk  = (const float*)d_in[5];
    const float* bk  = (const float*)d_in[6];
    const float* Wv  = (const float*)d_in[7];
    const float* bv  = (const float*)d_in[8];
    const float* Wo  = (const float*)d_in[9];
    const float* bo  = (const float*)d_in[10];
    float* out = (float*)d_out;

    __nv_bfloat16 *qh, *ql, *kh, *kl, *vth, *vtl, *chi, *clo, *xh, *xl, *wh, *wl;
    cudaGetSymbolAddress((void**)&qh, g_qh);
    cudaGetSymbolAddress((void**)&ql, g_ql);
    cudaGetSymbolAddress((void**)&kh, g_kh);
    cudaGetSymbolAddress((void**)&kl, g_kl);
    cudaGetSymbolAddress((void**)&vth, g_vth);
    cudaGetSymbolAddress((void**)&vtl, g_vtl);
    cudaGetSymbolAddress((void**)&chi, g_chi);
    cudaGetSymbolAddress((void**)&clo, g_clo);
    cudaGetSymbolAddress((void**)&xh, g_xh);
    cudaGetSymbolAddress((void**)&xl, g_xl);
    cudaGetSymbolAddress((void**)&wh, g_wh);
    cudaGetSymbolAddress((void**)&wl, g_wl);

    const size_t XSZ = (size_t)NM * NF;
    const size_t WSZ = (size_t)512 * 512;

    static int once = 0;
    if (!once) {
        cudaFuncSetAttribute(attn_fa2,
                             cudaFuncAttributeMaxDynamicSharedMemorySize, ATTN_BYTES);
        cudaFuncSetAttribute(proj_gemm,
                             cudaFuncAttributeMaxDynamicSharedMemorySize, GEMM_BYTES);
        cudaFuncSetAttribute(out_gemm,
                             cudaFuncAttributeMaxDynamicSharedMemorySize, GEMM_BYTES);
        once = 1;
    }

    SplitArgs sa;
    sa.src[0] = x_q; sa.src[1] = x_k; sa.src[2] = x_v;
    sa.src[3] = Wq;  sa.src[4] = Wk;  sa.src[5] = Wv; sa.src[6] = Wo;
    for (int i = 0; i < 3; i++) { sa.hi[i] = xh + i * XSZ; sa.lo[i] = xl + i * XSZ; }
    for (int i = 0; i < 4; i++) { sa.hi[3 + i] = wh + i * WSZ; sa.lo[3 + i] = wl + i * WSZ; }
    split_all<<<3328, 256>>>(sa);

    ProjArgs pa;
    for (int i = 0; i < 3; i++) {
        pa.xh[i] = xh + i * XSZ; pa.xl[i] = xl + i * XSZ;
        pa.wh[i] = wh + i * WSZ; pa.wl[i] = wl + i * WSZ;
    }
    pa.bias[0] = bq; pa.bias[1] = bk; pa.bias[2] = bv;
    pa.oh[0] = qh;  pa.ol[0] = ql;
    pa.oh[1] = kh;  pa.ol[1] = kl;
    pa.oh[2] = vth; pa.ol[2] = vtl;
    proj_gemm<<<dim3(NM / 128, 4, 3), 256, GEMM_BYTES>>>(pa);

    attn_fa2<<<dim3(NS / 128, NB * NH), 256, ATTN_BYTES>>>(qh, ql, kh, kl, vth, vtl, chi, clo);

    out_gemm<<<dim3(NM / 128, 4), 256, GEMM_BYTES>>>(chi, clo, wh + 3 * WSZ, wl + 3 * WSZ, bo, out);
}